// round 11
// baseline (speedup 1.0000x reference)
#include <cuda_runtime.h>
#include <cuda_fp16.h>
#include <math.h>
#include <stdint.h>

// Problem constants
#define MFFT 8192      // complex FFT size (packed real of N=16384)
#define MH   4096      // MFFT/2
#define LOGM 13
#define HDIM 512
#define BDIM 8
#define LDIM 8192

// Device scratch
__device__ float2   g_Kf[HDIM * 8193];                  // rfft(k, 16384) per h
__device__ uint32_t g_P[(size_t)BDIM * HDIM * LDIM];    // gelu result, fp16 (h, h) duplicated
__device__ uint32_t g_Wp[HDIM * HDIM];                  // W fp16 (hi, lo) split

__device__ __forceinline__ float2 cmulf2(float2 a, float2 b) {
    return make_float2(a.x * b.x - a.y * b.y, a.x * b.y + a.y * b.x);
}
__device__ __forceinline__ float2 caddf2(float2 a, float2 b) { return make_float2(a.x + b.x, a.y + b.y); }
__device__ __forceinline__ float2 csubf2(float2 a, float2 b) { return make_float2(a.x - b.x, a.y - b.y); }
__device__ __forceinline__ float2 conjf2(float2 a) { return make_float2(a.x, -a.y); }
__device__ __forceinline__ int rev13(int k) { return (int)(__brev((unsigned)k) >> 19); }

__device__ __forceinline__ uint32_t pack_w(float v) {
    __half h = __float2half_rn(v);
    __half l = __float2half_rn(v - __half2float(h));
    return (uint32_t)__half_as_ushort(h) | ((uint32_t)__half_as_ushort(l) << 16);
}
__device__ __forceinline__ uint32_t pack_g(float v) {
    uint32_t h = (uint32_t)__half_as_ushort(__float2half_rn(v));
    return h | (h << 16);
}

// Fused first forward pass from global input (upper half zero): s=0 with a2=a3=0.
__device__ __forceinline__ void load_pass1(float2* A, const float2* up, int tid) {
#pragma unroll
    for (int p = 0; p < 4; p++) {
        int g = tid + p * 512;
        float2 a0 = up[g];
        float2 a1 = up[g + 2048];
        float ang = (-6.283185307179586f / 8192.0f) * (float)g;
        float sn, cs; __sincosf(ang, &sn, &cs);
        float2 w1 = make_float2(cs, sn);
        float2 w2 = cmulf2(w1, w1);
        A[g]        = caddf2(a0, a1);
        A[g + 2048] = cmulf2(csubf2(a0, a1), w2);
        float2 m  = make_float2(a0.x + a1.y, a0.y - a1.x);   // a0 - i*a1
        A[g + 4096] = cmulf2(m, w1);
        float2 pq = make_float2(a0.x - a1.y, a0.y + a1.x);   // a0 + i*a1
        A[g + 6144] = cmulf2(cmulf2(pq, w1), w2);
    }
}

// Remaining fused double radix-2 DIF passes (s=2..10) + final radix-2.
__device__ void fft_forward_rest(float2* A, int tid) {
#pragma unroll
    for (int s = 2; s < 12; s += 2) {
        int ld2 = 11 - s;
        int d2 = 1 << ld2;
        int d1 = d2 << 1;
        __syncthreads();
#pragma unroll
        for (int p = 0; p < 4; p++) {
            int g = tid + p * 512;
            int tw = g & (d2 - 1);
            int i = ((g >> ld2) << (ld2 + 2)) + tw;
            float2 a0 = A[i], a1 = A[i + d2], a2 = A[i + d1], a3 = A[i + d1 + d2];
            float ang = (-6.283185307179586f / 8192.0f) * (float)(tw << s);
            float sn, cs; __sincosf(ang, &sn, &cs);
            float2 w1 = make_float2(cs, sn);
            float2 w2 = cmulf2(w1, w1);
            float2 s02 = caddf2(a0, a2), d02 = csubf2(a0, a2);
            float2 s13 = caddf2(a1, a3), d13 = csubf2(a1, a3);
            A[i]      = caddf2(s02, s13);
            A[i + d2] = cmulf2(csubf2(s02, s13), w2);
            float2 m  = make_float2(d02.x + d13.y, d02.y - d13.x);
            A[i + d1] = cmulf2(m, w1);
            float2 pq = make_float2(d02.x - d13.y, d02.y + d13.x);
            A[i + d1 + d2] = cmulf2(cmulf2(pq, w1), w2);
        }
    }
    __syncthreads();
#pragma unroll
    for (int p = 0; p < 8; p++) {
        int j = tid + p * 512;
        float2 a = A[2 * j], b = A[2 * j + 1];
        A[2 * j]     = caddf2(a, b);
        A[2 * j + 1] = csubf2(a, b);
    }
    __syncthreads();
}

// Inverse DIT, levels 0..10 only (final pair s=11 fused into the conv epilogue).
__device__ void fft_inverse_partial(float2* A, int tid) {
    __syncthreads();
#pragma unroll
    for (int p = 0; p < 8; p++) {
        int j = tid + p * 512;
        float2 a = A[2 * j], b = A[2 * j + 1];
        A[2 * j]     = caddf2(a, b);
        A[2 * j + 1] = csubf2(a, b);
    }
#pragma unroll
    for (int s = 1; s < 11; s += 2) {
        int d1 = 1 << s;
        int d2 = d1 << 1;
        __syncthreads();
#pragma unroll
        for (int p = 0; p < 4; p++) {
            int g = tid + p * 512;
            int tw = g & (d1 - 1);
            int i = ((g >> s) << (s + 2)) + tw;
            float2 a0 = A[i], a1 = A[i + d1], a2 = A[i + d2], a3 = A[i + d1 + d2];
            float ang = (6.283185307179586f / 8192.0f) * (float)(tw << (11 - s));
            float sn, cs; __sincosf(ang, &sn, &cs);
            float2 v0 = make_float2(cs, sn);
            float2 w  = cmulf2(v0, v0);
            float2 t1 = cmulf2(a1, w);
            float2 t3 = cmulf2(a3, w);
            float2 b0 = caddf2(a0, t1), b1 = csubf2(a0, t1);
            float2 b2 = caddf2(a2, t3), b3 = csubf2(a2, t3);
            float2 e  = cmulf2(b2, v0);
            float2 f  = cmulf2(b3, v0);
            A[i]           = caddf2(b0, e);
            A[i + d2]      = csubf2(b0, e);
            A[i + d1]      = make_float2(b1.x - f.y, b1.y + f.x);
            A[i + d1 + d2] = make_float2(b1.x + f.y, b1.y - f.x);
        }
    }
    __syncthreads();
}

// Kernel A: Kf[h] = rfft(k[h], 16384)
extern "C" __global__ void __launch_bounds__(512) kf_kernel(const float* __restrict__ kin) {
    extern __shared__ float2 sh[];
    float2* A = sh;
    int tid = threadIdx.x;
    int h = blockIdx.x;
    const float2* kp = (const float2*)(kin + (size_t)h * LDIM);
    load_pass1(A, kp, tid);
    fft_forward_rest(A, tid);
    float2* outp = g_Kf + (size_t)h * 8193;
    for (int k = tid; k < MH; k += 512) {
        if (k == 0) {
            float2 Z0 = A[0];
            outp[0]    = make_float2(Z0.x + Z0.y, 0.f);
            outp[8192] = make_float2(Z0.x - Z0.y, 0.f);
            outp[4096] = conjf2(A[1]);
        } else {
            float2 Zk = A[rev13(k)];
            float2 Zm = A[rev13(MFFT - k)];
            float2 cZm = conjf2(Zm);
            float2 E  = make_float2(0.5f * (Zk.x + cZm.x), 0.5f * (Zk.y + cZm.y));
            float2 Dd = csubf2(Zk, cZm);
            float2 O  = make_float2(0.5f * Dd.y, -0.5f * Dd.x);
            float ang = (-3.14159265358979323846f / 8192.0f) * (float)k;
            float sn, cs; __sincosf(ang, &sn, &cs);
            float2 Wt = make_float2(cs, sn);
            float2 WO = cmulf2(Wt, O);
            outp[k]        = caddf2(E, WO);
            outp[MFFT - k] = conjf2(csubf2(E, WO));
        }
    }
}

// Kernel B: conv + skip + gelu -> duplicated fp16 words; final inverse pass fused.
extern "C" __global__ void __launch_bounds__(512) conv_kernel(
    const float* __restrict__ u, const float* __restrict__ Dv) {
    extern __shared__ float2 sh[];
    float2* A = sh;
    int tid = threadIdx.x;
    int b = blockIdx.x & (BDIM - 1);
    int h = blockIdx.x >> 3;
    const float2* up = (const float2*)(u + ((size_t)b * HDIM + h) * LDIM);
    load_pass1(A, up, tid);
    fft_forward_rest(A, tid);

    const float2* Kf = g_Kf + (size_t)h * 8193;
    for (int k = tid; k < MH; k += 512) {
        if (k == 0) {
            float2 Z0 = A[0];
            float X0 = Z0.x + Z0.y;
            float XM = Z0.x - Z0.y;
            float2 K0 = Kf[0], KM = Kf[8192];
            float2 Y0 = make_float2(X0 * K0.x, X0 * K0.y);
            float2 YM = make_float2(XM * KM.x, XM * KM.y);
            float2 cYM = conjf2(YM);
            float2 Ep = make_float2(0.5f * (Y0.x + cYM.x), 0.5f * (Y0.y + cYM.y));
            float2 Op = make_float2(0.5f * (Y0.x - cYM.x), 0.5f * (Y0.y - cYM.y));
            A[0] = make_float2(Ep.x - Op.y, Ep.y + Op.x);
            float2 Zq = A[1];
            float2 Yq = cmulf2(conjf2(Zq), Kf[4096]);
            A[1] = conjf2(Yq);
        } else {
            int rk = rev13(k), rm = rev13(MFFT - k);
            float2 Zk = A[rk], Zm = A[rm];
            float2 cZm = conjf2(Zm);
            float2 E  = make_float2(0.5f * (Zk.x + cZm.x), 0.5f * (Zk.y + cZm.y));
            float2 Dd = csubf2(Zk, cZm);
            float2 O  = make_float2(0.5f * Dd.y, -0.5f * Dd.x);
            float ang = (-3.14159265358979323846f / 8192.0f) * (float)k;
            float sn, cs; __sincosf(ang, &sn, &cs);
            float2 Wt = make_float2(cs, sn);
            float2 WO = cmulf2(Wt, O);
            float2 Xk = caddf2(E, WO);
            float2 Xm = conjf2(csubf2(E, WO));
            float2 Yk = cmulf2(Xk, Kf[k]);
            float2 Ym = cmulf2(Xm, Kf[MFFT - k]);
            float2 cYm = conjf2(Ym);
            float2 Ep = make_float2(0.5f * (Yk.x + cYm.x), 0.5f * (Yk.y + cYm.y));
            float2 P  = make_float2(0.5f * (Yk.x - cYm.x), 0.5f * (Yk.y - cYm.y));
            float2 Op = cmulf2(conjf2(Wt), P);
            A[rk] = make_float2(Ep.x - Op.y, Ep.y + Op.x);
            A[rm] = make_float2(Ep.x + Op.y, Op.x - Ep.y);
        }
    }
    fft_inverse_partial(A, tid);

    // Fused final inverse pair (s=11: d1=2048, d2=4096; i=g) + skip + gelu + store.
    // Only outputs at indices g and g+2048 (< 4096) are needed.
    float Dh = Dv[h];
    uint2* gp = (uint2*)(g_P + ((size_t)b * HDIM + h) * LDIM);
    const float inv = 1.0f / (float)MFFT;
#pragma unroll
    for (int p = 0; p < 4; p++) {
        int g = tid + p * 512;
        float2 a0 = A[g], a1 = A[g + 2048], a2 = A[g + 4096], a3 = A[g + 6144];
        float ang = (6.283185307179586f / 8192.0f) * (float)g;
        float sn, cs; __sincosf(ang, &sn, &cs);
        float2 v0 = make_float2(cs, sn);
        float2 w  = cmulf2(v0, v0);
        float2 t1 = cmulf2(a1, w);
        float2 t3 = cmulf2(a3, w);
        float2 b0 = caddf2(a0, t1), b1 = csubf2(a0, t1);
        float2 b2 = caddf2(a2, t3), b3 = csubf2(a2, t3);
        float2 e  = cmulf2(b2, v0);
        float2 f  = cmulf2(b3, v0);
        float2 out0 = caddf2(b0, e);                         // -> complex slot g
        float2 out1 = make_float2(b1.x - f.y, b1.y + f.x);   // -> complex slot g+2048
        float2 uu0 = up[g], uu1 = up[g + 2048];
        float y0 = out0.x * inv + Dh * uu0.x;
        float y1 = out0.y * inv + Dh * uu0.y;
        float y2 = out1.x * inv + Dh * uu1.x;
        float y3 = out1.y * inv + Dh * uu1.y;
        float q0 = 0.5f * y0 * (1.0f + erff(y0 * 0.70710678118654752440f));
        float q1 = 0.5f * y1 * (1.0f + erff(y1 * 0.70710678118654752440f));
        float q2 = 0.5f * y2 * (1.0f + erff(y2 * 0.70710678118654752440f));
        float q3 = 0.5f * y3 * (1.0f + erff(y3 * 0.70710678118654752440f));
        gp[g]        = make_uint2(pack_g(q0), pack_g(q1));
        gp[g + 2048] = make_uint2(pack_g(q2), pack_g(q3));
    }
}

// W pack kernel
extern "C" __global__ void __launch_bounds__(256) wpack_kernel(const float* __restrict__ Wm) {
    int i = blockIdx.x * 256 + threadIdx.x;
    g_Wp[i] = pack_w(Wm[i]);
}

// ---------------- mma.sync GEMM, 3-stage cp.async pipeline (R7, proven) ----------------
__device__ __forceinline__ uint32_t smem_u32(const void* p) {
    return (uint32_t)__cvta_generic_to_shared(p);
}
__device__ __forceinline__ uint32_t swz(uint32_t off) { return off ^ ((off >> 3) & 0x70); }

__device__ __forceinline__ void ldmat4(uint32_t* r, uint32_t addr) {
    asm volatile("ldmatrix.sync.aligned.m8n8.x4.shared.b16 {%0,%1,%2,%3}, [%4];"
                 : "=r"(r[0]), "=r"(r[1]), "=r"(r[2]), "=r"(r[3]) : "r"(addr));
}
__device__ __forceinline__ void mma16816(float* d, const uint32_t* a, uint32_t b0, uint32_t b1) {
    asm volatile(
        "mma.sync.aligned.m16n8k16.row.col.f32.f16.f16.f32 "
        "{%0,%1,%2,%3}, {%4,%5,%6,%7}, {%8,%9}, {%0,%1,%2,%3};"
        : "+f"(d[0]), "+f"(d[1]), "+f"(d[2]), "+f"(d[3])
        : "r"(a[0]), "r"(a[1]), "r"(a[2]), "r"(a[3]), "r"(b0), "r"(b1));
}
#define CP16(dst, src) asm volatile("cp.async.cg.shared.global [%0], [%1], 16;" :: "r"(dst), "l"(src) : "memory")
#define CP4(dst, src)  asm volatile("cp.async.ca.shared.global [%0], [%1], 4;"  :: "r"(dst), "l"(src) : "memory")
#define CP_COMMIT()    asm volatile("cp.async.commit_group;" ::: "memory")
#define CP_WAIT1()     asm volatile("cp.async.wait_group 1;" ::: "memory")

extern "C" __global__ void __launch_bounds__(256, 2) gemm_mma_kernel(
    const float* __restrict__ bias, float* __restrict__ outp) {
    extern __shared__ char smem[];
    uint32_t sb = smem_u32(smem);
    int t = threadIdx.x;
    int lane = t & 31, wid = t >> 5;
    int warp_m = wid >> 2, warp_n = wid & 3;   // 2 x 4 warp grid; warp tile 64x32
    int o0 = blockIdx.x * 128, l0 = blockIdx.y * 128, b = blockIdx.z;

    int a_row = t >> 1, a_half = t & 1;
    const uint32_t* wp = g_Wp + (size_t)(o0 + a_row) * HDIM + a_half * 16;
    int b_l = t & 127, b_hg = (t >> 7) * 16;
    const uint32_t* gpB = g_P + (size_t)b * HDIM * LDIM + l0 + b_l;

    auto load_chunk = [&](int c) {
        int buf = c % 3;
        uint32_t sA = sb + buf * 32768;
        uint32_t sB = sA + 16384;
        const uint32_t* aw = wp + c * 32;
#pragma unroll
        for (int j = 0; j < 4; j++) {
            uint32_t off = (uint32_t)(a_row * 128 + (a_half * 16 + j * 4) * 4);
            CP16(sA + swz(off), aw + j * 4);
        }
#pragma unroll
        for (int q = 0; q < 16; q++) {
            int hw = b_hg + q;
            uint32_t off = (uint32_t)(b_l * 128 + hw * 4);
            CP4(sB + swz(off), gpB + (size_t)(c * 32 + hw) * LDIM);
        }
    };

    int a_lrow = (lane & 7) + ((lane >> 3) & 1) * 8;
    int a_lcol = (lane >> 4) * 16;
    int b_lrow = (lane & 7) + ((lane >> 4) & 1) * 8;
    int b_lcol = ((lane >> 3) & 1) * 16;
    uint32_t xorm = (uint32_t)((lane & 7) << 4);

    float acc[4][4][4];
#pragma unroll
    for (int i = 0; i < 4; i++)
#pragma unroll
        for (int j = 0; j < 4; j++)
#pragma unroll
            for (int q = 0; q < 4; q++) acc[i][j][q] = 0.f;

    load_chunk(0);
    CP_COMMIT();
    load_chunk(1);
    CP_COMMIT();

#pragma unroll 1
    for (int c = 0; c < 16; c++) {
        CP_WAIT1();
        __syncthreads();
        if (c + 2 < 16) load_chunk(c + 2);
        CP_COMMIT();
        int buf = c % 3;
        uint32_t sA = sb + buf * 32768;
        uint32_t sB = sA + 16384;
#pragma unroll
        for (int s = 0; s < 4; s++) {
            uint32_t afr[4][4];
#pragma unroll
            for (int mt = 0; mt < 4; mt++) {
                uint32_t off = (uint32_t)((warp_m * 64 + mt * 16 + a_lrow) * 128 + s * 32 + a_lcol);
                ldmat4(afr[mt], sA + (off ^ xorm));
            }
#pragma unroll
            for (int bt = 0; bt < 2; bt++) {
                uint32_t bfr[4];
                uint32_t off = (uint32_t)((warp_n * 32 + bt * 16 + b_lrow) * 128 + s * 32 + b_lcol);
                ldmat4(bfr, sB + (off ^ xorm));
#pragma unroll
                for (int mt = 0; mt < 4; mt++) {
                    mma16816(acc[mt][bt * 2 + 0], afr[mt], bfr[0], bfr[1]);
                    mma16816(acc[mt][bt * 2 + 1], afr[mt], bfr[2], bfr[3]);
                }
            }
        }
    }

#pragma unroll
    for (int mt = 0; mt < 4; mt++) {
        int r = o0 + warp_m * 64 + mt * 16 + (lane >> 2);
        float bs0 = bias[r], bs1 = bias[r + 8];
        float* p0 = outp + ((size_t)b * HDIM + r) * LDIM + l0 + warp_n * 32 + (lane & 3) * 2;
        float* p1 = p0 + 8 * LDIM;
#pragma unroll
        for (int nt = 0; nt < 4; nt++) {
            float2 v0 = make_float2(acc[mt][nt][0] + bs0, acc[mt][nt][1] + bs0);
            float2 v1 = make_float2(acc[mt][nt][2] + bs1, acc[mt][nt][3] + bs1);
            *(float2*)(p0 + nt * 8) = v0;
            *(float2*)(p1 + nt * 8) = v1;
        }
    }
}

extern "C" void kernel_launch(void* const* d_in, const int* in_sizes, int n_in,
                              void* d_out, int out_size) {
    const float* u    = (const float*)d_in[0];   // (8,512,8192)
    const float* kin  = (const float*)d_in[1];   // (1,512,8192)
    const float* Dv   = (const float*)d_in[2];   // (1,512)
    const float* Wm   = (const float*)d_in[3];   // (512,512)
    const float* bias = (const float*)d_in[4];   // (512,)
    float* outp = (float*)d_out;                 // (8,512,8192)

    size_t smem = (size_t)MFFT * sizeof(float2);  // 64 KB
    cudaFuncSetAttribute(kf_kernel,   cudaFuncAttributeMaxDynamicSharedMemorySize, (int)smem);
    cudaFuncSetAttribute(conv_kernel, cudaFuncAttributeMaxDynamicSharedMemorySize, (int)smem);
    size_t gsmem = 3 * 32768;                      // 96 KB (3-stage)
    cudaFuncSetAttribute(gemm_mma_kernel, cudaFuncAttributeMaxDynamicSharedMemorySize, (int)gsmem);

    wpack_kernel<<<HDIM * HDIM / 256, 256>>>(Wm);
    kf_kernel<<<HDIM, 512, smem>>>(kin);
    conv_kernel<<<BDIM * HDIM, 512, smem>>>(u, Dv);
    dim3 grid(HDIM / 128, LDIM / 128, BDIM);      // o fastest -> B-panel L2 reuse
    gemm_mma_kernel<<<grid, 256, gsmem>>>(bias, outp);
}

// round 12
// speedup vs baseline: 1.1399x; 1.1399x over previous
#include <cuda_runtime.h>
#include <cuda_fp16.h>
#include <math.h>
#include <stdint.h>

// Problem constants
#define MFFT 8192      // complex FFT size (packed real of N=16384)
#define MH   4096      // MFFT/2
#define HDIM 512
#define BDIM 8
#define LDIM 8192
#define C8   (6.283185307179586f / 8192.0f)
#define RS2  0.70710678118654752440f

// Device scratch
__device__ float2   g_Kf[HDIM * 8193];                  // rfft(k, 16384) per h
__device__ uint32_t g_P[(size_t)BDIM * HDIM * LDIM];    // gelu result, fp16 (h, h) duplicated
__device__ uint32_t g_Wp[HDIM * HDIM];                  // W fp16 (hi, lo) split

__device__ __forceinline__ float2 cmulf2(float2 a, float2 b) {
    return make_float2(a.x * b.x - a.y * b.y, a.x * b.y + a.y * b.x);
}
__device__ __forceinline__ float2 caddf2(float2 a, float2 b) { return make_float2(a.x + b.x, a.y + b.y); }
__device__ __forceinline__ float2 csubf2(float2 a, float2 b) { return make_float2(a.x - b.x, a.y - b.y); }
__device__ __forceinline__ float2 conjf2(float2 a) { return make_float2(a.x, -a.y); }
__device__ __forceinline__ int rev13(int k) { return (int)(__brev((unsigned)k) >> 19); }
__device__ __forceinline__ int phys(int i) { return i ^ ((i >> 5) & 31); }

__device__ __forceinline__ uint32_t pack_w(float v) {
    __half h = __float2half_rn(v);
    __half l = __float2half_rn(v - __half2float(h));
    return (uint32_t)__half_as_ushort(h) | ((uint32_t)__half_as_ushort(l) << 16);
}
__device__ __forceinline__ uint32_t pack_g(float v) {
    uint32_t h = (uint32_t)__half_as_ushort(__float2half_rn(v));
    return h | (h << 16);
}

// Proven radix-4 DIF body. Register order (i, i+d2, i+2d2, i+3d2). w1 = e^{-i*C8*(tw<<s)}.
__device__ __forceinline__ void r4f(float2& A0, float2& A1, float2& A2, float2& A3, float2 w1) {
    float2 w2 = cmulf2(w1, w1);
    float2 s02 = caddf2(A0, A2), d02 = csubf2(A0, A2);
    float2 s13 = caddf2(A1, A3), d13 = csubf2(A1, A3);
    A0 = caddf2(s02, s13);
    A1 = cmulf2(csubf2(s02, s13), w2);
    float2 m  = make_float2(d02.x + d13.y, d02.y - d13.x);
    A2 = cmulf2(m, w1);
    float2 pq = make_float2(d02.x - d13.y, d02.y + d13.x);
    A3 = cmulf2(cmulf2(pq, w1), w2);
}
// Proven radix-4 DIT body. Register order (i, i+d1, i+2d1, i+3d1). v0 = e^{+i*C8*(tw<<(11-s))}.
__device__ __forceinline__ void r4i(float2& A0, float2& A1, float2& A2, float2& A3, float2 v0) {
    float2 w  = cmulf2(v0, v0);
    float2 t1 = cmulf2(A1, w), t3 = cmulf2(A3, w);
    float2 b0 = caddf2(A0, t1), b1 = csubf2(A0, t1);
    float2 b2 = caddf2(A2, t3), b3 = csubf2(A2, t3);
    float2 e = cmulf2(b2, v0), f = cmulf2(b3, v0);
    A0 = caddf2(b0, e);
    A2 = csubf2(b0, e);
    A1 = make_float2(b1.x - f.y, b1.y + f.x);
    A3 = make_float2(b1.x + f.y, b1.y - f.x);
}
// Spectral pair: given Z[k], Z[M-k] (M=8192 packed FFT), produce Z'[k], Z'[M-k].
__device__ __forceinline__ void spectral_pair(int k, float2 Zk, float2 Zm, const float2* Kf,
                                              float2& outk, float2& outm) {
    float2 cZm = conjf2(Zm);
    float2 E = make_float2(0.5f * (Zk.x + cZm.x), 0.5f * (Zk.y + cZm.y));
    float2 Dd = csubf2(Zk, cZm);
    float2 O = make_float2(0.5f * Dd.y, -0.5f * Dd.x);
    float ang = (-3.14159265358979323846f / 8192.0f) * (float)k;
    float sn, cs; __sincosf(ang, &sn, &cs);
    float2 Wt = make_float2(cs, sn);
    float2 WO = cmulf2(Wt, O);
    float2 Xk = caddf2(E, WO);
    float2 Xm = conjf2(csubf2(E, WO));
    float2 Yk = cmulf2(Xk, Kf[k]);
    float2 Ym = cmulf2(Xm, Kf[MFFT - k]);
    float2 cYm = conjf2(Ym);
    float2 Ep = make_float2(0.5f * (Yk.x + cYm.x), 0.5f * (Yk.y + cYm.y));
    float2 P  = make_float2(0.5f * (Yk.x - cYm.x), 0.5f * (Yk.y - cYm.y));
    float2 Op = cmulf2(conjf2(Wt), P);
    outk = make_float2(Ep.x - Op.y, Ep.y + Op.x);
    outm = make_float2(Ep.x + Op.y, Op.x - Ep.y);
}

// ---------------- OLD full-array FFT machinery (kept for kf_kernel only) ----------------
__device__ __forceinline__ void load_pass1(float2* A, const float2* up, int tid) {
#pragma unroll
    for (int p = 0; p < 4; p++) {
        int g = tid + p * 512;
        float2 a0 = up[g];
        float2 a1 = up[g + 2048];
        float ang = -C8 * (float)g;
        float sn, cs; __sincosf(ang, &sn, &cs);
        float2 w1 = make_float2(cs, sn);
        float2 w2 = cmulf2(w1, w1);
        A[g]        = caddf2(a0, a1);
        A[g + 2048] = cmulf2(csubf2(a0, a1), w2);
        float2 m  = make_float2(a0.x + a1.y, a0.y - a1.x);
        A[g + 4096] = cmulf2(m, w1);
        float2 pq = make_float2(a0.x - a1.y, a0.y + a1.x);
        A[g + 6144] = cmulf2(cmulf2(pq, w1), w2);
    }
}
__device__ void fft_forward_rest(float2* A, int tid) {
#pragma unroll
    for (int s = 2; s < 12; s += 2) {
        int ld2 = 11 - s;
        int d2 = 1 << ld2;
        int d1 = d2 << 1;
        __syncthreads();
#pragma unroll
        for (int p = 0; p < 4; p++) {
            int g = tid + p * 512;
            int tw = g & (d2 - 1);
            int i = ((g >> ld2) << (ld2 + 2)) + tw;
            float ang = -C8 * (float)(tw << s);
            float sn, cs; __sincosf(ang, &sn, &cs);
            float2 w1 = make_float2(cs, sn);
            r4f(A[i], A[i + d2], A[i + d1], A[i + d1 + d2], w1);
        }
    }
    __syncthreads();
#pragma unroll
    for (int p = 0; p < 8; p++) {
        int j = tid + p * 512;
        float2 a = A[2 * j], b = A[2 * j + 1];
        A[2 * j]     = caddf2(a, b);
        A[2 * j + 1] = csubf2(a, b);
    }
    __syncthreads();
}

// Kernel A: Kf[h] = rfft(k[h], 16384)  (unchanged path)
extern "C" __global__ void __launch_bounds__(512) kf_kernel(const float* __restrict__ kin) {
    extern __shared__ float2 sh[];
    float2* A = sh;
    int tid = threadIdx.x;
    int h = blockIdx.x;
    const float2* kp = (const float2*)(kin + (size_t)h * LDIM);
    load_pass1(A, kp, tid);
    fft_forward_rest(A, tid);
    float2* outp = g_Kf + (size_t)h * 8193;
    for (int k = tid; k < MH; k += 512) {
        if (k == 0) {
            float2 Z0 = A[0];
            outp[0]    = make_float2(Z0.x + Z0.y, 0.f);
            outp[8192] = make_float2(Z0.x - Z0.y, 0.f);
            outp[4096] = conjf2(A[1]);
        } else {
            float2 Zk = A[rev13(k)];
            float2 Zm = A[rev13(MFFT - k)];
            float2 cZm = conjf2(Zm);
            float2 E  = make_float2(0.5f * (Zk.x + cZm.x), 0.5f * (Zk.y + cZm.y));
            float2 Dd = csubf2(Zk, cZm);
            float2 O  = make_float2(0.5f * Dd.y, -0.5f * Dd.x);
            float ang = (-3.14159265358979323846f / 8192.0f) * (float)k;
            float sn, cs; __sincosf(ang, &sn, &cs);
            float2 Wt = make_float2(cs, sn);
            float2 WO = cmulf2(Wt, O);
            outp[k]        = caddf2(E, WO);
            outp[MFFT - k] = conjf2(csubf2(E, WO));
        }
    }
}

// ---------------- Kernel B: register radix-16 conv ----------------
extern "C" __global__ void __launch_bounds__(512, 2) conv_kernel(
    const float* __restrict__ u, const float* __restrict__ Dv) {
    extern __shared__ float2 sh[];
    float2* S = sh;
    int tid = threadIdx.x;
    int b = blockIdx.x & (BDIM - 1);
    int h = blockIdx.x >> 3;
    const float2* up = (const float2*)(u + ((size_t)b * HDIM + h) * LDIM);
    float2 r[16];

    // ---- Phase A: load + forward levels 0-3 (s=0 simplified: upper half zero) ----
#pragma unroll
    for (int j = 0; j < 8; j++) r[j] = up[tid + 512 * j];
#pragma unroll
    for (int jp = 0; jp < 4; jp++) {
        int i = tid + 512 * jp;
        float2 a0 = r[jp], a1 = r[jp + 4];
        float sn, cs; __sincosf(-C8 * (float)i, &sn, &cs);
        float2 w1 = make_float2(cs, sn);
        float2 w2 = cmulf2(w1, w1);
        r[jp]      = caddf2(a0, a1);
        r[jp + 4]  = cmulf2(csubf2(a0, a1), w2);
        float2 m   = make_float2(a0.x + a1.y, a0.y - a1.x);
        r[jp + 8]  = cmulf2(m, w1);
        float2 pq  = make_float2(a0.x - a1.y, a0.y + a1.x);
        r[jp + 12] = cmulf2(cmulf2(pq, w1), w2);
    }
    {   // s=2: tw = tid for all quadruples
        float sn, cs; __sincosf(-C8 * (float)(tid << 2), &sn, &cs);
        float2 w1 = make_float2(cs, sn);
#pragma unroll
        for (int q = 0; q < 4; q++) r4f(r[4 * q], r[4 * q + 1], r[4 * q + 2], r[4 * q + 3], w1);
    }
#pragma unroll
    for (int j = 0; j < 16; j++) S[phys(tid + 512 * j)] = r[j];

    // ---- Phase B: forward levels 4-7 ----
    __syncthreads();
    {
        int bb = tid >> 5, t = tid & 31;
        int base = bb * 512 + t;
#pragma unroll
        for (int j = 0; j < 16; j++) r[j] = S[phys(base + 32 * j)];
#pragma unroll
        for (int jp = 0; jp < 4; jp++) {   // s=4, d2=128
            int tw = 32 * jp + t;
            float sn, cs; __sincosf(-C8 * (float)(tw << 4), &sn, &cs);
            float2 w1 = make_float2(cs, sn);
            r4f(r[jp], r[jp + 4], r[jp + 8], r[jp + 12], w1);
        }
        {   // s=6, d2=32: tw = t
            float sn, cs; __sincosf(-C8 * (float)(t << 6), &sn, &cs);
            float2 w1 = make_float2(cs, sn);
#pragma unroll
            for (int q = 0; q < 4; q++) r4f(r[4 * q], r[4 * q + 1], r[4 * q + 2], r[4 * q + 3], w1);
        }
#pragma unroll
        for (int j = 0; j < 16; j++) S[phys(base + 32 * j)] = r[j];
    }

    // ---- Phase C: forward levels 8-11 ----
    __syncthreads();
    {
        int b2 = tid >> 1, t2 = tid & 1;
        int base = 32 * b2 + t2;
#pragma unroll
        for (int j = 0; j < 16; j++) r[j] = S[phys(base + 2 * j)];
#pragma unroll
        for (int jp = 0; jp < 4; jp++) {   // s=8, d2=8
            int tw = 2 * jp + t2;
            float sn, cs; __sincosf(-C8 * (float)(tw << 8), &sn, &cs);
            float2 w1 = make_float2(cs, sn);
            r4f(r[jp], r[jp + 4], r[jp + 8], r[jp + 12], w1);
        }
        {   // s=10, d2=2: tw = t2; w1 = e^{-i pi/4 * t2}
            float2 w1 = t2 ? make_float2(RS2, -RS2) : make_float2(1.f, 0.f);
#pragma unroll
            for (int q = 0; q < 4; q++) r4f(r[4 * q], r[4 * q + 1], r[4 * q + 2], r[4 * q + 3], w1);
        }
#pragma unroll
        for (int j = 0; j < 16; j++) S[phys(base + 2 * j)] = r[j];
    }

    // ---- Spectral stage with fused forward level 12 (stride 1, no twiddle) ----
    // k<4096 => rev13(k) even; rev13(8192-k) odd. rev13(4096+x)=rev13(x)+1.
    __syncthreads();
    const float2* Kf = g_Kf + (size_t)h * 8193;
#pragma unroll 1
    for (int p = 0; p < 4; p++) {
        int k = tid + 512 * p;
        if (k == 0) {
            float2 P0 = S[phys(0)], P1 = S[phys(1)];
            float2 Z0 = caddf2(P0, P1);      // freq 0 / 8192 packed
            float2 Zq = csubf2(P0, P1);      // freq 4096 (slot 1)
            float X0 = Z0.x + Z0.y;
            float XM = Z0.x - Z0.y;
            float2 K0 = Kf[0], KM = Kf[8192];
            float2 Y0 = make_float2(X0 * K0.x, X0 * K0.y);
            float2 YM = make_float2(XM * KM.x, XM * KM.y);
            float2 cYM = conjf2(YM);
            float2 Ep = make_float2(0.5f * (Y0.x + cYM.x), 0.5f * (Y0.y + cYM.y));
            float2 Op = make_float2(0.5f * (Y0.x - cYM.x), 0.5f * (Y0.y - cYM.y));
            S[phys(0)] = make_float2(Ep.x - Op.y, Ep.y + Op.x);
            float2 Yq = cmulf2(conjf2(Zq), Kf[4096]);
            S[phys(1)] = conjf2(Yq);
            // k = 2048 self-paired group: slots 2,3
            float2 P2 = S[phys(2)], P3 = S[phys(3)];
            float2 Zk = caddf2(P2, P3);      // freq 2048
            float2 Zm = csubf2(P2, P3);      // freq 6144
            float2 ok, om;
            spectral_pair(2048, Zk, Zm, Kf, ok, om);
            S[phys(2)] = ok;
            S[phys(3)] = om;
        } else {
            int rk  = rev13(k);         // even
            int rkt = rev13(4096 - k);  // even
            float2 Pa = S[phys(rk)],  Pb = S[phys(rk + 1)];
            float2 Pc = S[phys(rkt)], Pd = S[phys(rkt + 1)];
            float2 Zk   = caddf2(Pa, Pb);   // freq k
            float2 ZMk  = csubf2(Pc, Pd);   // freq 8192-k  (slot rkt+1)
            float2 Zkt  = caddf2(Pc, Pd);   // freq 4096-k
            float2 ZMkt = csubf2(Pa, Pb);   // freq 4096+k  (slot rk+1)
            float2 o1k, o1m, o2k, o2m;
            spectral_pair(k, Zk, ZMk, Kf, o1k, o1m);
            spectral_pair(4096 - k, Zkt, ZMkt, Kf, o2k, o2m);
            S[phys(rk)]      = o1k;
            S[phys(rkt + 1)] = o1m;
            S[phys(rkt)]     = o2k;
            S[phys(rk + 1)]  = o2m;
        }
    }

    // ---- C-inv: inverse levels 0-3 ----
    __syncthreads();
    {
        int base = 16 * tid;
#pragma unroll
        for (int j = 0; j < 16; j++) r[j] = S[phys(base + j)];
        // level 0 (stride 1, no twiddle)
#pragma unroll
        for (int m2 = 0; m2 < 8; m2++) {
            float2 a = r[2 * m2], bq = r[2 * m2 + 1];
            r[2 * m2]     = caddf2(a, bq);
            r[2 * m2 + 1] = csubf2(a, bq);
        }
        // r4i s=1 (d1=2): quadruples (i,i+2,i+4,i+6); tw = i&1
#pragma unroll
        for (int q = 0; q < 2; q++)
#pragma unroll
            for (int tq = 0; tq < 2; tq++) {
                float2 v0 = tq ? make_float2(RS2, RS2) : make_float2(1.f, 0.f);
                int o = 8 * q + tq;
                r4i(r[o], r[o + 2], r[o + 4], r[o + 6], v0);
            }
        // level 3 (stride 8): pairs (j, j+8), twiddle e^{+i*C8*(j<<9)}
#pragma unroll
        for (int j = 0; j < 8; j++) {
            float sn, cs; __sincosf(C8 * (float)(j << 9), &sn, &cs);
            float2 wb = make_float2(cs, sn);
            float2 t = cmulf2(r[j + 8], wb);
            float2 a = r[j];
            r[j]     = caddf2(a, t);
            r[j + 8] = csubf2(a, t);
        }
#pragma unroll
        for (int j = 0; j < 16; j++) S[phys(base + j)] = r[j];
    }

    // ---- B-inv: inverse levels 4-7 ----
    __syncthreads();
    {
        int c = tid >> 4, i0 = tid & 15;
        int base = 256 * c + i0;
#pragma unroll
        for (int j = 0; j < 16; j++) r[j] = S[phys(base + 16 * j)];
        {   // s=4 (d1=16): tw = i0
            float sn, cs; __sincosf(C8 * (float)(i0 << 7), &sn, &cs);
            float2 v0 = make_float2(cs, sn);
#pragma unroll
            for (int q = 0; q < 4; q++) r4i(r[4 * q], r[4 * q + 1], r[4 * q + 2], r[4 * q + 3], v0);
        }
#pragma unroll
        for (int jp = 0; jp < 4; jp++) {   // s=6 (d1=64): tw = 16*jp + i0
            float sn, cs; __sincosf(C8 * (float)((16 * jp + i0) << 5), &sn, &cs);
            float2 v0 = make_float2(cs, sn);
            r4i(r[jp], r[jp + 4], r[jp + 8], r[jp + 12], v0);
        }
#pragma unroll
        for (int j = 0; j < 16; j++) S[phys(base + 16 * j)] = r[j];
    }

    // ---- A-inv: inverse levels 8-11 ----
    __syncthreads();
    {
        int e = tid >> 8, i1 = tid & 255;
        int base = 4096 * e + i1;
#pragma unroll
        for (int j = 0; j < 16; j++) r[j] = S[phys(base + 256 * j)];
        {   // s=8 (d1=256): tw = i1
            float sn, cs; __sincosf(C8 * (float)(i1 << 3), &sn, &cs);
            float2 v0 = make_float2(cs, sn);
#pragma unroll
            for (int q = 0; q < 4; q++) r4i(r[4 * q], r[4 * q + 1], r[4 * q + 2], r[4 * q + 3], v0);
        }
#pragma unroll
        for (int jp = 0; jp < 4; jp++) {   // s=10 (d1=1024): tw = 256*jp + i1
            float sn, cs; __sincosf(C8 * (float)((256 * jp + i1) << 1), &sn, &cs);
            float2 v0 = make_float2(cs, sn);
            r4i(r[jp], r[jp + 4], r[jp + 8], r[jp + 12], v0);
        }
#pragma unroll
        for (int j = 0; j < 16; j++) S[phys(base + 256 * j)] = r[j];
    }

    // ---- Epilogue: inverse level 12 (stride 4096) + skip + gelu + store ----
    __syncthreads();
    float Dh = Dv[h];
    uint2* gp = (uint2*)(g_P + ((size_t)b * HDIM + h) * LDIM);
    const float inv = 1.0f / (float)MFFT;
#pragma unroll
    for (int p = 0; p < 8; p++) {
        int g = tid + 512 * p;
        float2 a = S[phys(g)], bq = S[phys(g + 4096)];
        float sn, cs; __sincosf(C8 * (float)g, &sn, &cs);
        float2 wb = make_float2(cs, sn);
        float2 t = cmulf2(bq, wb);
        float2 X = caddf2(a, t);            // time samples (y[2g], y[2g+1]) unnormalized
        float2 uu = up[g];
        float y0 = X.x * inv + Dh * uu.x;
        float y1 = X.y * inv + Dh * uu.y;
        float q0 = 0.5f * y0 * (1.0f + erff(y0 * 0.70710678118654752440f));
        float q1 = 0.5f * y1 * (1.0f + erff(y1 * 0.70710678118654752440f));
        gp[g] = make_uint2(pack_g(q0), pack_g(q1));
    }
}

// W pack kernel
extern "C" __global__ void __launch_bounds__(256) wpack_kernel(const float* __restrict__ Wm) {
    int i = blockIdx.x * 256 + threadIdx.x;
    g_Wp[i] = pack_w(Wm[i]);
}

// ---------------- mma.sync GEMM, 3-stage cp.async pipeline (R7, proven) ----------------
__device__ __forceinline__ uint32_t smem_u32(const void* p) {
    return (uint32_t)__cvta_generic_to_shared(p);
}
__device__ __forceinline__ uint32_t swz(uint32_t off) { return off ^ ((off >> 3) & 0x70); }

__device__ __forceinline__ void ldmat4(uint32_t* r, uint32_t addr) {
    asm volatile("ldmatrix.sync.aligned.m8n8.x4.shared.b16 {%0,%1,%2,%3}, [%4];"
                 : "=r"(r[0]), "=r"(r[1]), "=r"(r[2]), "=r"(r[3]) : "r"(addr));
}
__device__ __forceinline__ void mma16816(float* d, const uint32_t* a, uint32_t b0, uint32_t b1) {
    asm volatile(
        "mma.sync.aligned.m16n8k16.row.col.f32.f16.f16.f32 "
        "{%0,%1,%2,%3}, {%4,%5,%6,%7}, {%8,%9}, {%0,%1,%2,%3};"
        : "+f"(d[0]), "+f"(d[1]), "+f"(d[2]), "+f"(d[3])
        : "r"(a[0]), "r"(a[1]), "r"(a[2]), "r"(a[3]), "r"(b0), "r"(b1));
}
#define CP16(dst, src) asm volatile("cp.async.cg.shared.global [%0], [%1], 16;" :: "r"(dst), "l"(src) : "memory")
#define CP4(dst, src)  asm volatile("cp.async.ca.shared.global [%0], [%1], 4;"  :: "r"(dst), "l"(src) : "memory")
#define CP_COMMIT()    asm volatile("cp.async.commit_group;" ::: "memory")
#define CP_WAIT1()     asm volatile("cp.async.wait_group 1;" ::: "memory")

extern "C" __global__ void __launch_bounds__(256, 2) gemm_mma_kernel(
    const float* __restrict__ bias, float* __restrict__ outp) {
    extern __shared__ char smem[];
    uint32_t sb = smem_u32(smem);
    int t = threadIdx.x;
    int lane = t & 31, wid = t >> 5;
    int warp_m = wid >> 2, warp_n = wid & 3;
    int o0 = blockIdx.x * 128, l0 = blockIdx.y * 128, b = blockIdx.z;

    int a_row = t >> 1, a_half = t & 1;
    const uint32_t* wp = g_Wp + (size_t)(o0 + a_row) * HDIM + a_half * 16;
    int b_l = t & 127, b_hg = (t >> 7) * 16;
    const uint32_t* gpB = g_P + (size_t)b * HDIM * LDIM + l0 + b_l;

    auto load_chunk = [&](int c) {
        int buf = c % 3;
        uint32_t sA = sb + buf * 32768;
        uint32_t sB = sA + 16384;
        const uint32_t* aw = wp + c * 32;
#pragma unroll
        for (int j = 0; j < 4; j++) {
            uint32_t off = (uint32_t)(a_row * 128 + (a_half * 16 + j * 4) * 4);
            CP16(sA + swz(off), aw + j * 4);
        }
#pragma unroll
        for (int q = 0; q < 16; q++) {
            int hw = b_hg + q;
            uint32_t off = (uint32_t)(b_l * 128 + hw * 4);
            CP4(sB + swz(off), gpB + (size_t)(c * 32 + hw) * LDIM);
        }
    };

    int a_lrow = (lane & 7) + ((lane >> 3) & 1) * 8;
    int a_lcol = (lane >> 4) * 16;
    int b_lrow = (lane & 7) + ((lane >> 4) & 1) * 8;
    int b_lcol = ((lane >> 3) & 1) * 16;
    uint32_t xorm = (uint32_t)((lane & 7) << 4);

    float acc[4][4][4];
#pragma unroll
    for (int i = 0; i < 4; i++)
#pragma unroll
        for (int j = 0; j < 4; j++)
#pragma unroll
            for (int q = 0; q < 4; q++) acc[i][j][q] = 0.f;

    load_chunk(0);
    CP_COMMIT();
    load_chunk(1);
    CP_COMMIT();

#pragma unroll 1
    for (int c = 0; c < 16; c++) {
        CP_WAIT1();
        __syncthreads();
        if (c + 2 < 16) load_chunk(c + 2);
        CP_COMMIT();
        int buf = c % 3;
        uint32_t sA = sb + buf * 32768;
        uint32_t sB = sA + 16384;
#pragma unroll
        for (int s = 0; s < 4; s++) {
            uint32_t afr[4][4];
#pragma unroll
            for (int mt = 0; mt < 4; mt++) {
                uint32_t off = (uint32_t)((warp_m * 64 + mt * 16 + a_lrow) * 128 + s * 32 + a_lcol);
                ldmat4(afr[mt], sA + (off ^ xorm));
            }
#pragma unroll
            for (int bt = 0; bt < 2; bt++) {
                uint32_t bfr[4];
                uint32_t off = (uint32_t)((warp_n * 32 + bt * 16 + b_lrow) * 128 + s * 32 + b_lcol);
                ldmat4(bfr, sB + (off ^ xorm));
#pragma unroll
                for (int mt = 0; mt < 4; mt++) {
                    mma16816(acc[mt][bt * 2 + 0], afr[mt], bfr[0], bfr[1]);
                    mma16816(acc[mt][bt * 2 + 1], afr[mt], bfr[2], bfr[3]);
                }
            }
        }
    }

#pragma unroll
    for (int mt = 0; mt < 4; mt++) {
        int r = o0 + warp_m * 64 + mt * 16 + (lane >> 2);
        float bs0 = bias[r], bs1 = bias[r + 8];
        float* p0 = outp + ((size_t)b * HDIM + r) * LDIM + l0 + warp_n * 32 + (lane & 3) * 2;
        float* p1 = p0 + 8 * LDIM;
#pragma unroll
        for (int nt = 0; nt < 4; nt++) {
            float2 v0 = make_float2(acc[mt][nt][0] + bs0, acc[mt][nt][1] + bs0);
            float2 v1 = make_float2(acc[mt][nt][2] + bs1, acc[mt][nt][3] + bs1);
            *(float2*)(p0 + nt * 8) = v0;
            *(float2*)(p1 + nt * 8) = v1;
        }
    }
}

extern "C" void kernel_launch(void* const* d_in, const int* in_sizes, int n_in,
                              void* d_out, int out_size) {
    const float* u    = (const float*)d_in[0];   // (8,512,8192)
    const float* kin  = (const float*)d_in[1];   // (1,512,8192)
    const float* Dv   = (const float*)d_in[2];   // (1,512)
    const float* Wm   = (const float*)d_in[3];   // (512,512)
    const float* bias = (const float*)d_in[4];   // (512,)
    float* outp = (float*)d_out;                 // (8,512,8192)

    size_t smem = (size_t)MFFT * sizeof(float2);  // 64 KB
    cudaFuncSetAttribute(kf_kernel,   cudaFuncAttributeMaxDynamicSharedMemorySize, (int)smem);
    cudaFuncSetAttribute(conv_kernel, cudaFuncAttributeMaxDynamicSharedMemorySize, (int)smem);
    size_t gsmem = 3 * 32768;                      // 96 KB (3-stage)
    cudaFuncSetAttribute(gemm_mma_kernel, cudaFuncAttributeMaxDynamicSharedMemorySize, (int)gsmem);

    wpack_kernel<<<HDIM * HDIM / 256, 256>>>(Wm);
    kf_kernel<<<HDIM, 512, smem>>>(kin);
    conv_kernel<<<BDIM * HDIM, 512, smem>>>(u, Dv);
    dim3 grid(HDIM / 128, LDIM / 128, BDIM);
    gemm_mma_kernel<<<grid, 256, gsmem>>>(bias, outp);
}

// round 13
// speedup vs baseline: 1.2530x; 1.0992x over previous
#include <cuda_runtime.h>
#include <cuda_fp16.h>
#include <math.h>
#include <stdint.h>

// Problem constants
#define MFFT 8192      // complex FFT size (packed real of N=16384)
#define MH   4096      // MFFT/2
#define HDIM 512
#define BDIM 8
#define LDIM 8192
#define C8   (6.283185307179586f / 8192.0f)
#define RS2  0.70710678118654752440f

// Device scratch
__device__ float2 g_Kf[HDIM * 8193];                       // rfft(k, 16384) per h
__device__ __half g_T[(size_t)BDIM * 64 * HDIM * 128];     // g fp16, [b][l/128][h][l%128]
__device__ __half g_Whl[(size_t)HDIM * 16 * 64];           // W fp16 [o][chunk][hi32|lo32]

__device__ __forceinline__ float2 cmulf2(float2 a, float2 b) {
    return make_float2(a.x * b.x - a.y * b.y, a.x * b.y + a.y * b.x);
}
__device__ __forceinline__ float2 caddf2(float2 a, float2 b) { return make_float2(a.x + b.x, a.y + b.y); }
__device__ __forceinline__ float2 csubf2(float2 a, float2 b) { return make_float2(a.x - b.x, a.y - b.y); }
__device__ __forceinline__ float2 conjf2(float2 a) { return make_float2(a.x, -a.y); }
__device__ __forceinline__ int rev13(int k) { return (int)(__brev((unsigned)k) >> 19); }
__device__ __forceinline__ int phys(int i) { return i ^ ((i >> 5) & 31); }

// Proven radix-4 DIF body.
__device__ __forceinline__ void r4f(float2& A0, float2& A1, float2& A2, float2& A3, float2 w1) {
    float2 w2 = cmulf2(w1, w1);
    float2 s02 = caddf2(A0, A2), d02 = csubf2(A0, A2);
    float2 s13 = caddf2(A1, A3), d13 = csubf2(A1, A3);
    A0 = caddf2(s02, s13);
    A1 = cmulf2(csubf2(s02, s13), w2);
    float2 m  = make_float2(d02.x + d13.y, d02.y - d13.x);
    A2 = cmulf2(m, w1);
    float2 pq = make_float2(d02.x - d13.y, d02.y + d13.x);
    A3 = cmulf2(cmulf2(pq, w1), w2);
}
// Proven radix-4 DIT body.
__device__ __forceinline__ void r4i(float2& A0, float2& A1, float2& A2, float2& A3, float2 v0) {
    float2 w  = cmulf2(v0, v0);
    float2 t1 = cmulf2(A1, w), t3 = cmulf2(A3, w);
    float2 b0 = caddf2(A0, t1), b1 = csubf2(A0, t1);
    float2 b2 = caddf2(A2, t3), b3 = csubf2(A2, t3);
    float2 e = cmulf2(b2, v0), f = cmulf2(b3, v0);
    A0 = caddf2(b0, e);
    A2 = csubf2(b0, e);
    A1 = make_float2(b1.x - f.y, b1.y + f.x);
    A3 = make_float2(b1.x + f.y, b1.y - f.x);
}
__device__ __forceinline__ void spectral_pair(int k, float2 Zk, float2 Zm, const float2* Kf,
                                              float2& outk, float2& outm) {
    float2 cZm = conjf2(Zm);
    float2 E = make_float2(0.5f * (Zk.x + cZm.x), 0.5f * (Zk.y + cZm.y));
    float2 Dd = csubf2(Zk, cZm);
    float2 O = make_float2(0.5f * Dd.y, -0.5f * Dd.x);
    float ang = (-3.14159265358979323846f / 8192.0f) * (float)k;
    float sn, cs; __sincosf(ang, &sn, &cs);
    float2 Wt = make_float2(cs, sn);
    float2 WO = cmulf2(Wt, O);
    float2 Xk = caddf2(E, WO);
    float2 Xm = conjf2(csubf2(E, WO));
    float2 Yk = cmulf2(Xk, Kf[k]);
    float2 Ym = cmulf2(Xm, Kf[MFFT - k]);
    float2 cYm = conjf2(Ym);
    float2 Ep = make_float2(0.5f * (Yk.x + cYm.x), 0.5f * (Yk.y + cYm.y));
    float2 P  = make_float2(0.5f * (Yk.x - cYm.x), 0.5f * (Yk.y - cYm.y));
    float2 Op = cmulf2(conjf2(Wt), P);
    outk = make_float2(Ep.x - Op.y, Ep.y + Op.x);
    outm = make_float2(Ep.x + Op.y, Op.x - Ep.y);
}

// ---------------- full-array FFT (kf_kernel only) ----------------
__device__ __forceinline__ void load_pass1(float2* A, const float2* up, int tid) {
#pragma unroll
    for (int p = 0; p < 4; p++) {
        int g = tid + p * 512;
        float2 a0 = up[g];
        float2 a1 = up[g + 2048];
        float sn, cs; __sincosf(-C8 * (float)g, &sn, &cs);
        float2 w1 = make_float2(cs, sn);
        float2 w2 = cmulf2(w1, w1);
        A[g]        = caddf2(a0, a1);
        A[g + 2048] = cmulf2(csubf2(a0, a1), w2);
        float2 m  = make_float2(a0.x + a1.y, a0.y - a1.x);
        A[g + 4096] = cmulf2(m, w1);
        float2 pq = make_float2(a0.x - a1.y, a0.y + a1.x);
        A[g + 6144] = cmulf2(cmulf2(pq, w1), w2);
    }
}
__device__ void fft_forward_rest(float2* A, int tid) {
#pragma unroll
    for (int s = 2; s < 12; s += 2) {
        int ld2 = 11 - s;
        int d2 = 1 << ld2;
        int d1 = d2 << 1;
        __syncthreads();
#pragma unroll
        for (int p = 0; p < 4; p++) {
            int g = tid + p * 512;
            int tw = g & (d2 - 1);
            int i = ((g >> ld2) << (ld2 + 2)) + tw;
            float sn, cs; __sincosf(-C8 * (float)(tw << s), &sn, &cs);
            r4f(A[i], A[i + d2], A[i + d1], A[i + d1 + d2], make_float2(cs, sn));
        }
    }
    __syncthreads();
#pragma unroll
    for (int p = 0; p < 8; p++) {
        int j = tid + p * 512;
        float2 a = A[2 * j], b = A[2 * j + 1];
        A[2 * j]     = caddf2(a, b);
        A[2 * j + 1] = csubf2(a, b);
    }
    __syncthreads();
}

extern "C" __global__ void __launch_bounds__(512) kf_kernel(const float* __restrict__ kin) {
    extern __shared__ float2 sh[];
    float2* A = sh;
    int tid = threadIdx.x;
    int h = blockIdx.x;
    const float2* kp = (const float2*)(kin + (size_t)h * LDIM);
    load_pass1(A, kp, tid);
    fft_forward_rest(A, tid);
    float2* outp = g_Kf + (size_t)h * 8193;
    for (int k = tid; k < MH; k += 512) {
        if (k == 0) {
            float2 Z0 = A[0];
            outp[0]    = make_float2(Z0.x + Z0.y, 0.f);
            outp[8192] = make_float2(Z0.x - Z0.y, 0.f);
            outp[4096] = conjf2(A[1]);
        } else {
            float2 Zk = A[rev13(k)];
            float2 Zm = A[rev13(MFFT - k)];
            float2 cZm = conjf2(Zm);
            float2 E  = make_float2(0.5f * (Zk.x + cZm.x), 0.5f * (Zk.y + cZm.y));
            float2 Dd = csubf2(Zk, cZm);
            float2 O  = make_float2(0.5f * Dd.y, -0.5f * Dd.x);
            float ang = (-3.14159265358979323846f / 8192.0f) * (float)k;
            float sn, cs; __sincosf(ang, &sn, &cs);
            float2 Wt = make_float2(cs, sn);
            float2 WO = cmulf2(Wt, O);
            outp[k]        = caddf2(E, WO);
            outp[MFFT - k] = conjf2(csubf2(E, WO));
        }
    }
}

// ---------------- Kernel B: register radix-16 conv (R12, proven) ----------------
extern "C" __global__ void __launch_bounds__(512, 2) conv_kernel(
    const float* __restrict__ u, const float* __restrict__ Dv) {
    extern __shared__ float2 sh[];
    float2* S = sh;
    int tid = threadIdx.x;
    int b = blockIdx.x & (BDIM - 1);
    int h = blockIdx.x >> 3;
    const float2* up = (const float2*)(u + ((size_t)b * HDIM + h) * LDIM);
    float2 r[16];

    // Phase A: load + forward levels 0-3
#pragma unroll
    for (int j = 0; j < 8; j++) r[j] = up[tid + 512 * j];
#pragma unroll
    for (int jp = 0; jp < 4; jp++) {
        int i = tid + 512 * jp;
        float2 a0 = r[jp], a1 = r[jp + 4];
        float sn, cs; __sincosf(-C8 * (float)i, &sn, &cs);
        float2 w1 = make_float2(cs, sn);
        float2 w2 = cmulf2(w1, w1);
        r[jp]      = caddf2(a0, a1);
        r[jp + 4]  = cmulf2(csubf2(a0, a1), w2);
        float2 m   = make_float2(a0.x + a1.y, a0.y - a1.x);
        r[jp + 8]  = cmulf2(m, w1);
        float2 pq  = make_float2(a0.x - a1.y, a0.y + a1.x);
        r[jp + 12] = cmulf2(cmulf2(pq, w1), w2);
    }
    {
        float sn, cs; __sincosf(-C8 * (float)(tid << 2), &sn, &cs);
        float2 w1 = make_float2(cs, sn);
#pragma unroll
        for (int q = 0; q < 4; q++) r4f(r[4 * q], r[4 * q + 1], r[4 * q + 2], r[4 * q + 3], w1);
    }
#pragma unroll
    for (int j = 0; j < 16; j++) S[phys(tid + 512 * j)] = r[j];

    // Phase B: forward levels 4-7
    __syncthreads();
    {
        int bb = tid >> 5, t = tid & 31;
        int base = bb * 512 + t;
#pragma unroll
        for (int j = 0; j < 16; j++) r[j] = S[phys(base + 32 * j)];
#pragma unroll
        for (int jp = 0; jp < 4; jp++) {
            int tw = 32 * jp + t;
            float sn, cs; __sincosf(-C8 * (float)(tw << 4), &sn, &cs);
            r4f(r[jp], r[jp + 4], r[jp + 8], r[jp + 12], make_float2(cs, sn));
        }
        {
            float sn, cs; __sincosf(-C8 * (float)(t << 6), &sn, &cs);
            float2 w1 = make_float2(cs, sn);
#pragma unroll
            for (int q = 0; q < 4; q++) r4f(r[4 * q], r[4 * q + 1], r[4 * q + 2], r[4 * q + 3], w1);
        }
#pragma unroll
        for (int j = 0; j < 16; j++) S[phys(base + 32 * j)] = r[j];
    }

    // Phase C: forward levels 8-11
    __syncthreads();
    {
        int b2 = tid >> 1, t2 = tid & 1;
        int base = 32 * b2 + t2;
#pragma unroll
        for (int j = 0; j < 16; j++) r[j] = S[phys(base + 2 * j)];
#pragma unroll
        for (int jp = 0; jp < 4; jp++) {
            int tw = 2 * jp + t2;
            float sn, cs; __sincosf(-C8 * (float)(tw << 8), &sn, &cs);
            r4f(r[jp], r[jp + 4], r[jp + 8], r[jp + 12], make_float2(cs, sn));
        }
        {
            float2 w1 = t2 ? make_float2(RS2, -RS2) : make_float2(1.f, 0.f);
#pragma unroll
            for (int q = 0; q < 4; q++) r4f(r[4 * q], r[4 * q + 1], r[4 * q + 2], r[4 * q + 3], w1);
        }
#pragma unroll
        for (int j = 0; j < 16; j++) S[phys(base + 2 * j)] = r[j];
    }

    // Spectral stage + fused forward level 12
    __syncthreads();
    const float2* Kf = g_Kf + (size_t)h * 8193;
#pragma unroll 1
    for (int p = 0; p < 4; p++) {
        int k = tid + 512 * p;
        if (k == 0) {
            float2 P0 = S[phys(0)], P1 = S[phys(1)];
            float2 Z0 = caddf2(P0, P1);
            float2 Zq = csubf2(P0, P1);
            float X0 = Z0.x + Z0.y;
            float XM = Z0.x - Z0.y;
            float2 K0 = Kf[0], KM = Kf[8192];
            float2 Y0 = make_float2(X0 * K0.x, X0 * K0.y);
            float2 YM = make_float2(XM * KM.x, XM * KM.y);
            float2 cYM = conjf2(YM);
            float2 Ep = make_float2(0.5f * (Y0.x + cYM.x), 0.5f * (Y0.y + cYM.y));
            float2 Op = make_float2(0.5f * (Y0.x - cYM.x), 0.5f * (Y0.y - cYM.y));
            S[phys(0)] = make_float2(Ep.x - Op.y, Ep.y + Op.x);
            float2 Yq = cmulf2(conjf2(Zq), Kf[4096]);
            S[phys(1)] = conjf2(Yq);
            float2 P2 = S[phys(2)], P3 = S[phys(3)];
            float2 Zk = caddf2(P2, P3);
            float2 Zm = csubf2(P2, P3);
            float2 ok, om;
            spectral_pair(2048, Zk, Zm, Kf, ok, om);
            S[phys(2)] = ok;
            S[phys(3)] = om;
        } else {
            int rk  = rev13(k);
            int rkt = rev13(4096 - k);
            float2 Pa = S[phys(rk)],  Pb = S[phys(rk + 1)];
            float2 Pc = S[phys(rkt)], Pd = S[phys(rkt + 1)];
            float2 Zk   = caddf2(Pa, Pb);
            float2 ZMk  = csubf2(Pc, Pd);
            float2 Zkt  = caddf2(Pc, Pd);
            float2 ZMkt = csubf2(Pa, Pb);
            float2 o1k, o1m, o2k, o2m;
            spectral_pair(k, Zk, ZMk, Kf, o1k, o1m);
            spectral_pair(4096 - k, Zkt, ZMkt, Kf, o2k, o2m);
            S[phys(rk)]      = o1k;
            S[phys(rkt + 1)] = o1m;
            S[phys(rkt)]     = o2k;
            S[phys(rk + 1)]  = o2m;
        }
    }

    // C-inv: inverse levels 0-3
    __syncthreads();
    {
        int base = 16 * tid;
#pragma unroll
        for (int j = 0; j < 16; j++) r[j] = S[phys(base + j)];
#pragma unroll
        for (int m2 = 0; m2 < 8; m2++) {
            float2 a = r[2 * m2], bq = r[2 * m2 + 1];
            r[2 * m2]     = caddf2(a, bq);
            r[2 * m2 + 1] = csubf2(a, bq);
        }
#pragma unroll
        for (int q = 0; q < 2; q++)
#pragma unroll
            for (int tq = 0; tq < 2; tq++) {
                float2 v0 = tq ? make_float2(RS2, RS2) : make_float2(1.f, 0.f);
                int o = 8 * q + tq;
                r4i(r[o], r[o + 2], r[o + 4], r[o + 6], v0);
            }
#pragma unroll
        for (int j = 0; j < 8; j++) {
            float sn, cs; __sincosf(C8 * (float)(j << 9), &sn, &cs);
            float2 wb = make_float2(cs, sn);
            float2 t = cmulf2(r[j + 8], wb);
            float2 a = r[j];
            r[j]     = caddf2(a, t);
            r[j + 8] = csubf2(a, t);
        }
#pragma unroll
        for (int j = 0; j < 16; j++) S[phys(base + j)] = r[j];
    }

    // B-inv: inverse levels 4-7
    __syncthreads();
    {
        int c = tid >> 4, i0 = tid & 15;
        int base = 256 * c + i0;
#pragma unroll
        for (int j = 0; j < 16; j++) r[j] = S[phys(base + 16 * j)];
        {
            float sn, cs; __sincosf(C8 * (float)(i0 << 7), &sn, &cs);
            float2 v0 = make_float2(cs, sn);
#pragma unroll
            for (int q = 0; q < 4; q++) r4i(r[4 * q], r[4 * q + 1], r[4 * q + 2], r[4 * q + 3], v0);
        }
#pragma unroll
        for (int jp = 0; jp < 4; jp++) {
            float sn, cs; __sincosf(C8 * (float)((16 * jp + i0) << 5), &sn, &cs);
            r4i(r[jp], r[jp + 4], r[jp + 8], r[jp + 12], make_float2(cs, sn));
        }
#pragma unroll
        for (int j = 0; j < 16; j++) S[phys(base + 16 * j)] = r[j];
    }

    // A-inv: inverse levels 8-11
    __syncthreads();
    {
        int e = tid >> 8, i1 = tid & 255;
        int base = 4096 * e + i1;
#pragma unroll
        for (int j = 0; j < 16; j++) r[j] = S[phys(base + 256 * j)];
        {
            float sn, cs; __sincosf(C8 * (float)(i1 << 3), &sn, &cs);
            float2 v0 = make_float2(cs, sn);
#pragma unroll
            for (int q = 0; q < 4; q++) r4i(r[4 * q], r[4 * q + 1], r[4 * q + 2], r[4 * q + 3], v0);
        }
#pragma unroll
        for (int jp = 0; jp < 4; jp++) {
            float sn, cs; __sincosf(C8 * (float)((256 * jp + i1) << 1), &sn, &cs);
            r4i(r[jp], r[jp + 4], r[jp + 8], r[jp + 12], make_float2(cs, sn));
        }
#pragma unroll
        for (int j = 0; j < 16; j++) S[phys(base + 256 * j)] = r[j];
    }

    // Epilogue: inverse level 12 + skip + gelu -> g_T [b][l/128][h][l%128] fp16
    __syncthreads();
    float Dh = Dv[h];
    const float inv = 1.0f / (float)MFFT;
#pragma unroll
    for (int p = 0; p < 8; p++) {
        int g = tid + 512 * p;
        float2 a = S[phys(g)], bq = S[phys(g + 4096)];
        float sn, cs; __sincosf(C8 * (float)g, &sn, &cs);
        float2 wb = make_float2(cs, sn);
        float2 t = cmulf2(bq, wb);
        float2 X = caddf2(a, t);              // time samples (y[2g], y[2g+1])
        float2 uu = up[g];
        float y0 = X.x * inv + Dh * uu.x;
        float y1 = X.y * inv + Dh * uu.y;
        float q0 = 0.5f * y0 * (1.0f + erff(y0 * 0.70710678118654752440f));
        float q1 = 0.5f * y1 * (1.0f + erff(y1 * 0.70710678118654752440f));
        // l = 2g, 2g+1 -> tile lt = g>>6, word index g&63
        __half2* gt = (__half2*)g_T + (((size_t)b * 64 + (g >> 6)) * HDIM + h) * 64 + (g & 63);
        *gt = __floats2half2_rn(q0, q1);
    }
}

// W pack: g_Whl[o][c][0..31] = hi(h=32c+q), [c][32..63] = lo
extern "C" __global__ void __launch_bounds__(256) wpack_kernel(const float* __restrict__ Wm) {
    int i = blockIdx.x * 256 + threadIdx.x;
    int o = i >> 9, h = i & 511;
    float v = Wm[i];
    __half hi = __float2half_rn(v);
    __half lo = __float2half_rn(v - __half2float(hi));
    g_Whl[((size_t)o * 16 + (h >> 5)) * 64 + (h & 31)]      = hi;
    g_Whl[((size_t)o * 16 + (h >> 5)) * 64 + 32 + (h & 31)] = lo;
}

// ---------------- mma.sync GEMM: trans-B, two-pass hi/lo split ----------------
__device__ __forceinline__ uint32_t smem_u32(const void* p) {
    return (uint32_t)__cvta_generic_to_shared(p);
}
__device__ __forceinline__ uint32_t swz(uint32_t off) { return off ^ ((off >> 3) & 0x70); }
__device__ __forceinline__ uint32_t swzB(uint32_t row, uint32_t colb) {
    return row * 256 + (colb ^ ((row & 7) << 4));
}

__device__ __forceinline__ void ldmat4(uint32_t* r, uint32_t addr) {
    asm volatile("ldmatrix.sync.aligned.m8n8.x4.shared.b16 {%0,%1,%2,%3}, [%4];"
                 : "=r"(r[0]), "=r"(r[1]), "=r"(r[2]), "=r"(r[3]) : "r"(addr));
}
__device__ __forceinline__ void ldmat4t(uint32_t* r, uint32_t addr) {
    asm volatile("ldmatrix.sync.aligned.m8n8.x4.trans.shared.b16 {%0,%1,%2,%3}, [%4];"
                 : "=r"(r[0]), "=r"(r[1]), "=r"(r[2]), "=r"(r[3]) : "r"(addr));
}
__device__ __forceinline__ void mma16816(float* d, const uint32_t* a, uint32_t b0, uint32_t b1) {
    asm volatile(
        "mma.sync.aligned.m16n8k16.row.col.f32.f16.f16.f32 "
        "{%0,%1,%2,%3}, {%4,%5,%6,%7}, {%8,%9}, {%0,%1,%2,%3};"
        : "+f"(d[0]), "+f"(d[1]), "+f"(d[2]), "+f"(d[3])
        : "r"(a[0]), "r"(a[1]), "r"(a[2]), "r"(a[3]), "r"(b0), "r"(b1));
}
#define CP16(dst, src) asm volatile("cp.async.cg.shared.global [%0], [%1], 16;" :: "r"(dst), "l"(src) : "memory")
#define CP_COMMIT()    asm volatile("cp.async.commit_group;" ::: "memory")
#define CP_WAIT1()     asm volatile("cp.async.wait_group 1;" ::: "memory")

// Per chunk c (32 h): A tile [o=128][hi32|lo32 fp16] = 16KB (128B rows, swz);
// B tile [kh=32][l=128 fp16] = 8KB (256B rows, swzB). 3 stages x 24KB = 72KB.
extern "C" __global__ void __launch_bounds__(256, 2) gemm_mma_kernel(
    const float* __restrict__ bias, float* __restrict__ outp) {
    extern __shared__ char smem[];
    uint32_t sb = smem_u32(smem);
    int t = threadIdx.x;
    int lane = t & 31, wid = t >> 5;
    int warp_m = wid >> 2, warp_n = wid & 3;   // 2 x 4 warp grid; warp tile 64x32
    int o0 = blockIdx.x * 128, l0 = blockIdx.y * 128, b = blockIdx.z;

    int a_row = t >> 1, a_half = t & 1;
    const __half* wp = g_Whl + (size_t)(o0 + a_row) * 1024 + a_half * 32;
    int b_row = t >> 3, b_cj = (t & 7) * 2;    // B: row kh, 16B-chunk pair
    const __half* gpB = g_T + ((size_t)b * 64 + blockIdx.y) * HDIM * 128;

    auto load_chunk = [&](int c) {
        int buf = c % 3;
        uint32_t sA = sb + buf * 24576;
        uint32_t sB = sA + 16384;
        const __half* aw = wp + c * 64;
#pragma unroll
        for (int j = 0; j < 4; j++) {
            uint32_t off = (uint32_t)(a_row * 128 + a_half * 64 + j * 16);
            CP16(sA + swz(off), aw + j * 8);
        }
        const __half* brow = gpB + (size_t)(c * 32 + b_row) * 128 + b_cj * 8;
#pragma unroll
        for (int e2 = 0; e2 < 2; e2++) {
            CP16(sB + swzB((uint32_t)b_row, (uint32_t)((b_cj + e2) * 16)), brow + e2 * 8);
        }
    };

    int a_lrow = (lane & 7) + ((lane >> 3) & 1) * 8;
    int a_lcol = (lane >> 4) * 16;
    uint32_t xorm = (uint32_t)((lane & 7) << 4);
    // B trans fragment addressing on [kh][l]: row = k0 + (lane&7) + 8*((lane>>3)&1),
    // col bytes = 2*(n0 + 8*(lane>>4))
    int bt_row = (lane & 7) + 8 * ((lane >> 3) & 1);
    int bt_colb = 16 * (lane >> 4);

    float acc[4][4][4];
#pragma unroll
    for (int i = 0; i < 4; i++)
#pragma unroll
        for (int j = 0; j < 4; j++)
#pragma unroll
            for (int q = 0; q < 4; q++) acc[i][j][q] = 0.f;

    load_chunk(0);
    CP_COMMIT();
    load_chunk(1);
    CP_COMMIT();

#pragma unroll 1
    for (int c = 0; c < 16; c++) {
        CP_WAIT1();
        __syncthreads();
        if (c + 2 < 16) load_chunk(c + 2);
        CP_COMMIT();
        int buf = c % 3;
        uint32_t sA = sb + buf * 24576;
        uint32_t sB = sA + 16384;
#pragma unroll
        for (int s = 0; s < 2; s++) {      // two k16 steps (kh 16s..16s+15)
            uint32_t ahi[4][4], alo[4][4];
#pragma unroll
            for (int mt = 0; mt < 4; mt++) {
                uint32_t offh = (uint32_t)((warp_m * 64 + mt * 16 + a_lrow) * 128 + s * 32 + a_lcol);
                uint32_t offl = offh + 64;
                ldmat4(ahi[mt], sA + (offh ^ xorm));
                ldmat4(alo[mt], sA + (offl ^ xorm));
            }
#pragma unroll
            for (int bt = 0; bt < 2; bt++) {   // n16 blocks
                uint32_t bfr[4];
                uint32_t row = (uint32_t)(16 * s + bt_row);
                uint32_t colb = (uint32_t)(2 * (warp_n * 32 + bt * 16) + bt_colb);
                ldmat4t(bfr, sB + swzB(row, colb));
#pragma unroll
                for (int mt = 0; mt < 4; mt++) {
                    mma16816(acc[mt][bt * 2 + 0], ahi[mt], bfr[0], bfr[1]);
                    mma16816(acc[mt][bt * 2 + 0], alo[mt], bfr[0], bfr[1]);
                    mma16816(acc[mt][bt * 2 + 1], ahi[mt], bfr[2], bfr[3]);
                    mma16816(acc[mt][bt * 2 + 1], alo[mt], bfr[2], bfr[3]);
                }
            }
        }
    }

    // Epilogue: acc[mt][nt]: rows r, r+8; cols nt*8 + (lane&3)*2
#pragma unroll
    for (int mt = 0; mt < 4; mt++) {
        int r = o0 + warp_m * 64 + mt * 16 + (lane >> 2);
        float bs0 = bias[r], bs1 = bias[r + 8];
        float* p0 = outp + ((size_t)b * HDIM + r) * LDIM + l0 + warp_n * 32 + (lane & 3) * 2;
        float* p1 = p0 + 8 * LDIM;
#pragma unroll
        for (int nt = 0; nt < 4; nt++) {
            float2 v0 = make_float2(acc[mt][nt][0] + bs0, acc[mt][nt][1] + bs0);
            float2 v1 = make_float2(acc[mt][nt][2] + bs1, acc[mt][nt][3] + bs1);
            *(float2*)(p0 + nt * 8) = v0;
            *(float2*)(p1 + nt * 8) = v1;
        }
    }
}

extern "C" void kernel_launch(void* const* d_in, const int* in_sizes, int n_in,
                              void* d_out, int out_size) {
    const float* u    = (const float*)d_in[0];   // (8,512,8192)
    const float* kin  = (const float*)d_in[1];   // (1,512,8192)
    const float* Dv   = (const float*)d_in[2];   // (1,512)
    const float* Wm   = (const float*)d_in[3];   // (512,512)
    const float* bias = (const float*)d_in[4];   // (512,)
    float* outp = (float*)d_out;                 // (8,512,8192)

    size_t smem = (size_t)MFFT * sizeof(float2);  // 64 KB
    cudaFuncSetAttribute(kf_kernel,   cudaFuncAttributeMaxDynamicSharedMemorySize, (int)smem);
    cudaFuncSetAttribute(conv_kernel, cudaFuncAttributeMaxDynamicSharedMemorySize, (int)smem);
    size_t gsmem = 3 * 24576;                      // 72 KB
    cudaFuncSetAttribute(gemm_mma_kernel, cudaFuncAttributeMaxDynamicSharedMemorySize, (int)gsmem);

    wpack_kernel<<<HDIM * HDIM / 256, 256>>>(Wm);
    kf_kernel<<<HDIM, 512, smem>>>(kin);
    conv_kernel<<<BDIM * HDIM, 512, smem>>>(u, Dv);
    dim3 grid(HDIM / 128, LDIM / 128, BDIM);
    gemm_mma_kernel<<<grid, 256, gsmem>>>(bias, outp);
}

// round 14
// speedup vs baseline: 1.2884x; 1.0283x over previous
#include <cuda_runtime.h>
#include <cuda_fp16.h>
#include <math.h>
#include <stdint.h>

// Problem constants
#define MFFT 8192      // complex FFT size (packed real of N=16384)
#define MH   4096      // MFFT/2
#define HDIM 512
#define BDIM 8
#define LDIM 8192
#define C8   (6.283185307179586f / 8192.0f)
#define RS2  0.70710678118654752440f
// rho = e^{-i*pi/8} (forward chain step); conj for inverse
#define RHO_C 0.92387953251128675613f
#define RHO_S 0.38268343236508977173f
// e^{-i*pi/16} (phase C base for t2=1)
#define P16_C 0.98078528040323044913f
#define P16_S 0.19509032201612826785f

// Device scratch
__device__ float2 g_Kf[HDIM * 8193];                       // rfft(k, 16384) per h
__device__ __half g_T[(size_t)BDIM * 64 * HDIM * 128];     // g fp16, [b][l/128][h][l%128]
__device__ __half g_Whl[(size_t)HDIM * 16 * 64];           // W fp16 [o][chunk][hi32|lo32]

__device__ __forceinline__ float2 cmulf2(float2 a, float2 b) {
    return make_float2(a.x * b.x - a.y * b.y, a.x * b.y + a.y * b.x);
}
__device__ __forceinline__ float2 caddf2(float2 a, float2 b) { return make_float2(a.x + b.x, a.y + b.y); }
__device__ __forceinline__ float2 csubf2(float2 a, float2 b) { return make_float2(a.x - b.x, a.y - b.y); }
__device__ __forceinline__ float2 conjf2(float2 a) { return make_float2(a.x, -a.y); }
__device__ __forceinline__ int rev13(int k) { return (int)(__brev((unsigned)k) >> 19); }
__device__ __forceinline__ int phys(int i) { return i ^ ((i >> 5) & 31); }

// Proven radix-4 DIF body.
__device__ __forceinline__ void r4f(float2& A0, float2& A1, float2& A2, float2& A3, float2 w1) {
    float2 w2 = cmulf2(w1, w1);
    float2 s02 = caddf2(A0, A2), d02 = csubf2(A0, A2);
    float2 s13 = caddf2(A1, A3), d13 = csubf2(A1, A3);
    A0 = caddf2(s02, s13);
    A1 = cmulf2(csubf2(s02, s13), w2);
    float2 m  = make_float2(d02.x + d13.y, d02.y - d13.x);
    A2 = cmulf2(m, w1);
    float2 pq = make_float2(d02.x - d13.y, d02.y + d13.x);
    A3 = cmulf2(cmulf2(pq, w1), w2);
}
// Proven radix-4 DIT body.
__device__ __forceinline__ void r4i(float2& A0, float2& A1, float2& A2, float2& A3, float2 v0) {
    float2 w  = cmulf2(v0, v0);
    float2 t1 = cmulf2(A1, w), t3 = cmulf2(A3, w);
    float2 b0 = caddf2(A0, t1), b1 = csubf2(A0, t1);
    float2 b2 = caddf2(A2, t3), b3 = csubf2(A2, t3);
    float2 e = cmulf2(b2, v0), f = cmulf2(b3, v0);
    A0 = caddf2(b0, e);
    A2 = csubf2(b0, e);
    A1 = make_float2(b1.x - f.y, b1.y + f.x);
    A3 = make_float2(b1.x + f.y, b1.y - f.x);
}
__device__ __forceinline__ void spectral_pair(int k, float2 Zk, float2 Zm, const float2* Kf,
                                              float2& outk, float2& outm) {
    float2 cZm = conjf2(Zm);
    float2 E = make_float2(0.5f * (Zk.x + cZm.x), 0.5f * (Zk.y + cZm.y));
    float2 Dd = csubf2(Zk, cZm);
    float2 O = make_float2(0.5f * Dd.y, -0.5f * Dd.x);
    float ang = (-3.14159265358979323846f / 8192.0f) * (float)k;
    float sn, cs; __sincosf(ang, &sn, &cs);
    float2 Wt = make_float2(cs, sn);
    float2 WO = cmulf2(Wt, O);
    float2 Xk = caddf2(E, WO);
    float2 Xm = conjf2(csubf2(E, WO));
    float2 Yk = cmulf2(Xk, Kf[k]);
    float2 Ym = cmulf2(Xm, Kf[MFFT - k]);
    float2 cYm = conjf2(Ym);
    float2 Ep = make_float2(0.5f * (Yk.x + cYm.x), 0.5f * (Yk.y + cYm.y));
    float2 P  = make_float2(0.5f * (Yk.x - cYm.x), 0.5f * (Yk.y - cYm.y));
    float2 Op = cmulf2(conjf2(Wt), P);
    outk = make_float2(Ep.x - Op.y, Ep.y + Op.x);
    outm = make_float2(Ep.x + Op.y, Op.x - Ep.y);
}

// ---------------- full-array FFT (kf_kernel only) ----------------
__device__ __forceinline__ void load_pass1(float2* A, const float2* up, int tid) {
#pragma unroll
    for (int p = 0; p < 4; p++) {
        int g = tid + p * 512;
        float2 a0 = up[g];
        float2 a1 = up[g + 2048];
        float sn, cs; __sincosf(-C8 * (float)g, &sn, &cs);
        float2 w1 = make_float2(cs, sn);
        float2 w2 = cmulf2(w1, w1);
        A[g]        = caddf2(a0, a1);
        A[g + 2048] = cmulf2(csubf2(a0, a1), w2);
        float2 m  = make_float2(a0.x + a1.y, a0.y - a1.x);
        A[g + 4096] = cmulf2(m, w1);
        float2 pq = make_float2(a0.x - a1.y, a0.y + a1.x);
        A[g + 6144] = cmulf2(cmulf2(pq, w1), w2);
    }
}
__device__ void fft_forward_rest(float2* A, int tid) {
#pragma unroll
    for (int s = 2; s < 12; s += 2) {
        int ld2 = 11 - s;
        int d2 = 1 << ld2;
        int d1 = d2 << 1;
        __syncthreads();
#pragma unroll
        for (int p = 0; p < 4; p++) {
            int g = tid + p * 512;
            int tw = g & (d2 - 1);
            int i = ((g >> ld2) << (ld2 + 2)) + tw;
            float sn, cs; __sincosf(-C8 * (float)(tw << s), &sn, &cs);
            r4f(A[i], A[i + d2], A[i + d1], A[i + d1 + d2], make_float2(cs, sn));
        }
    }
    __syncthreads();
#pragma unroll
    for (int p = 0; p < 8; p++) {
        int j = tid + p * 512;
        float2 a = A[2 * j], b = A[2 * j + 1];
        A[2 * j]     = caddf2(a, b);
        A[2 * j + 1] = csubf2(a, b);
    }
    __syncthreads();
}

extern "C" __global__ void __launch_bounds__(512) kf_kernel(const float* __restrict__ kin) {
    extern __shared__ float2 sh[];
    float2* A = sh;
    int tid = threadIdx.x;
    int h = blockIdx.x;
    const float2* kp = (const float2*)(kin + (size_t)h * LDIM);
    load_pass1(A, kp, tid);
    fft_forward_rest(A, tid);
    float2* outp = g_Kf + (size_t)h * 8193;
    for (int k = tid; k < MH; k += 512) {
        if (k == 0) {
            float2 Z0 = A[0];
            outp[0]    = make_float2(Z0.x + Z0.y, 0.f);
            outp[8192] = make_float2(Z0.x - Z0.y, 0.f);
            outp[4096] = conjf2(A[1]);
        } else {
            float2 Zk = A[rev13(k)];
            float2 Zm = A[rev13(MFFT - k)];
            float2 cZm = conjf2(Zm);
            float2 E  = make_float2(0.5f * (Zk.x + cZm.x), 0.5f * (Zk.y + cZm.y));
            float2 Dd = csubf2(Zk, cZm);
            float2 O  = make_float2(0.5f * Dd.y, -0.5f * Dd.x);
            float ang = (-3.14159265358979323846f / 8192.0f) * (float)k;
            float sn, cs; __sincosf(ang, &sn, &cs);
            float2 Wt = make_float2(cs, sn);
            float2 WO = cmulf2(Wt, O);
            outp[k]        = caddf2(E, WO);
            outp[MFFT - k] = conjf2(csubf2(E, WO));
        }
    }
}

// ---------------- Kernel B: register radix-16 conv, hoisted swizzle + twiddle chains ----
extern "C" __global__ void __launch_bounds__(512, 2) conv_kernel(
    const float* __restrict__ u, const float* __restrict__ Dv) {
    extern __shared__ float2 sh[];
    float2* S = sh;
    int tid = threadIdx.x;
    int b = blockIdx.x & (BDIM - 1);
    int h = blockIdx.x >> 3;
    const float2* up = (const float2*)(u + ((size_t)b * HDIM + h) * LDIM);
    float2 r[16];
    const float2 RHO  = make_float2(RHO_C, -RHO_S);   // e^{-i pi/8}
    const float2 RHOc = make_float2(RHO_C,  RHO_S);   // e^{+i pi/8}

    // ---- Phase A: load + forward levels 0-3 ----
#pragma unroll
    for (int j = 0; j < 8; j++) r[j] = up[tid + 512 * j];
    float2 wA;
    { float sn, cs; __sincosf(-C8 * (float)tid, &sn, &cs); wA = make_float2(cs, sn); }
    {
        float2 w = wA;
#pragma unroll
        for (int jp = 0; jp < 4; jp++) {
            float2 a0 = r[jp], a1 = r[jp + 4];
            float2 w1 = w, w2 = cmulf2(w, w);
            r[jp]      = caddf2(a0, a1);
            r[jp + 4]  = cmulf2(csubf2(a0, a1), w2);
            float2 m   = make_float2(a0.x + a1.y, a0.y - a1.x);
            r[jp + 8]  = cmulf2(m, w1);
            float2 pq  = make_float2(a0.x - a1.y, a0.y + a1.x);
            r[jp + 12] = cmulf2(cmulf2(pq, w1), w2);
            w = cmulf2(w, RHO);
        }
        float2 w4 = cmulf2(wA, wA); w4 = cmulf2(w4, w4);   // e^{-i C8 * (tid<<2)}
#pragma unroll
        for (int q = 0; q < 4; q++) r4f(r[4 * q], r[4 * q + 1], r[4 * q + 2], r[4 * q + 3], w4);
    }
    {
        int pA = tid ^ (tid >> 5);
#pragma unroll
        for (int j = 0; j < 16; j++) S[(pA ^ ((j & 1) << 4)) + 512 * j] = r[j];
    }

    // ---- Phase B: forward levels 4-7 ----
    __syncthreads();
    {
        int bb = tid >> 5, t = tid & 31;
        int baseB = bb * 512;
        int tb = t ^ ((bb & 1) << 4);
#pragma unroll
        for (int j = 0; j < 16; j++) r[j] = S[baseB + 32 * j + (tb ^ j)];
        float2 wB;
        { float sn, cs; __sincosf(-C8 * (float)(t << 4), &sn, &cs); wB = make_float2(cs, sn); }
        {
            float2 w = wB;
#pragma unroll
            for (int jp = 0; jp < 4; jp++) {
                r4f(r[jp], r[jp + 4], r[jp + 8], r[jp + 12], w);
                w = cmulf2(w, RHO);
            }
        }
        float2 w4 = cmulf2(wB, wB); w4 = cmulf2(w4, w4);   // e^{-i C8 * (t<<6)}
#pragma unroll
        for (int q = 0; q < 4; q++) r4f(r[4 * q], r[4 * q + 1], r[4 * q + 2], r[4 * q + 3], w4);
#pragma unroll
        for (int j = 0; j < 16; j++) S[baseB + 32 * j + (tb ^ j)] = r[j];
    }

    // ---- Phase C: forward levels 8-11 ----
    __syncthreads();
    {
        int b2 = tid >> 1, t2 = tid & 1;
        int baseC = 32 * b2;
        int mC0 = b2 & 31;
#pragma unroll
        for (int j = 0; j < 16; j++) r[j] = S[baseC + ((2 * j + t2) ^ mC0)];
        {
            float2 w = t2 ? make_float2(P16_C, -P16_S) : make_float2(1.f, 0.f);
#pragma unroll
            for (int jp = 0; jp < 4; jp++) {
                r4f(r[jp], r[jp + 4], r[jp + 8], r[jp + 12], w);
                w = cmulf2(w, RHO);
            }
        }
        {
            float2 w1 = t2 ? make_float2(RS2, -RS2) : make_float2(1.f, 0.f);
#pragma unroll
            for (int q = 0; q < 4; q++) r4f(r[4 * q], r[4 * q + 1], r[4 * q + 2], r[4 * q + 3], w1);
        }
#pragma unroll
        for (int j = 0; j < 16; j++) S[baseC + ((2 * j + t2) ^ mC0)] = r[j];
    }

    // ---- Spectral stage + fused forward level 12 ----
    __syncthreads();
    const float2* Kf = g_Kf + (size_t)h * 8193;
#pragma unroll 1
    for (int p = 0; p < 4; p++) {
        int k = tid + 512 * p;
        if (k == 0) {
            float2 P0 = S[phys(0)], P1 = S[phys(1)];
            float2 Z0 = caddf2(P0, P1);
            float2 Zq = csubf2(P0, P1);
            float X0 = Z0.x + Z0.y;
            float XM = Z0.x - Z0.y;
            float2 K0 = Kf[0], KM = Kf[8192];
            float2 Y0 = make_float2(X0 * K0.x, X0 * K0.y);
            float2 YM = make_float2(XM * KM.x, XM * KM.y);
            float2 cYM = conjf2(YM);
            float2 Ep = make_float2(0.5f * (Y0.x + cYM.x), 0.5f * (Y0.y + cYM.y));
            float2 Op = make_float2(0.5f * (Y0.x - cYM.x), 0.5f * (Y0.y - cYM.y));
            S[phys(0)] = make_float2(Ep.x - Op.y, Ep.y + Op.x);
            float2 Yq = cmulf2(conjf2(Zq), Kf[4096]);
            S[phys(1)] = conjf2(Yq);
            float2 P2 = S[phys(2)], P3 = S[phys(3)];
            float2 Zk = caddf2(P2, P3);
            float2 Zm = csubf2(P2, P3);
            float2 ok, om;
            spectral_pair(2048, Zk, Zm, Kf, ok, om);
            S[phys(2)] = ok;
            S[phys(3)] = om;
        } else {
            int rk  = rev13(k);
            int rkt = rev13(4096 - k);
            float2 Pa = S[phys(rk)],  Pb = S[phys(rk + 1)];
            float2 Pc = S[phys(rkt)], Pd = S[phys(rkt + 1)];
            float2 Zk   = caddf2(Pa, Pb);
            float2 ZMk  = csubf2(Pc, Pd);
            float2 Zkt  = caddf2(Pc, Pd);
            float2 ZMkt = csubf2(Pa, Pb);
            float2 o1k, o1m, o2k, o2m;
            spectral_pair(k, Zk, ZMk, Kf, o1k, o1m);
            spectral_pair(4096 - k, Zkt, ZMkt, Kf, o2k, o2m);
            S[phys(rk)]      = o1k;
            S[phys(rkt + 1)] = o1m;
            S[phys(rkt)]     = o2k;
            S[phys(rk + 1)]  = o2m;
        }
    }

    // ---- C-inv: inverse levels 0-3 ----
    __syncthreads();
    {
        int baseCi = 32 * (tid >> 1);
        int mm = (16 * (tid & 1)) ^ ((tid >> 1) & 31);
#pragma unroll
        for (int j = 0; j < 16; j++) r[j] = S[baseCi + (j ^ mm)];
#pragma unroll
        for (int m2 = 0; m2 < 8; m2++) {
            float2 a = r[2 * m2], bq = r[2 * m2 + 1];
            r[2 * m2]     = caddf2(a, bq);
            r[2 * m2 + 1] = csubf2(a, bq);
        }
#pragma unroll
        for (int q = 0; q < 2; q++)
#pragma unroll
            for (int tq = 0; tq < 2; tq++) {
                float2 v0 = tq ? make_float2(RS2, RS2) : make_float2(1.f, 0.f);
                int o = 8 * q + tq;
                r4i(r[o], r[o + 2], r[o + 4], r[o + 6], v0);
            }
        {   // level 3: wb = e^{+i C8 * 512 * j}, chained
            float2 wb = make_float2(1.f, 0.f);
#pragma unroll
            for (int j = 0; j < 8; j++) {
                float2 t = cmulf2(r[j + 8], wb);
                float2 a = r[j];
                r[j]     = caddf2(a, t);
                r[j + 8] = csubf2(a, t);
                wb = cmulf2(wb, RHOc);
            }
        }
#pragma unroll
        for (int j = 0; j < 16; j++) S[baseCi + (j ^ mm)] = r[j];
    }

    // ---- B-inv: inverse levels 4-7 ----
    __syncthreads();
    {
        int c = tid >> 4, i0 = tid & 15;
        int baseBi = 256 * c;
        int mB = i0 ^ (8 * (c & 3));
#pragma unroll
        for (int j = 0; j < 16; j++)
            r[j] = S[baseBi + 32 * (j >> 1) + (mB ^ ((16 * (j & 1)) | (j >> 1)))];
        float2 qB;
        { float sn, cs; __sincosf(C8 * (float)(i0 << 5), &sn, &cs); qB = make_float2(cs, sn); }
        {
            float2 v0 = cmulf2(qB, qB); v0 = cmulf2(v0, v0);   // e^{+i C8*(i0<<7)}
#pragma unroll
            for (int q = 0; q < 4; q++) r4i(r[4 * q], r[4 * q + 1], r[4 * q + 2], r[4 * q + 3], v0);
        }
        {
            float2 v = qB;
#pragma unroll
            for (int jp = 0; jp < 4; jp++) {
                r4i(r[jp], r[jp + 4], r[jp + 8], r[jp + 12], v);
                v = cmulf2(v, RHOc);
            }
        }
#pragma unroll
        for (int j = 0; j < 16; j++)
            S[baseBi + 32 * (j >> 1) + (mB ^ ((16 * (j & 1)) | (j >> 1)))] = r[j];
    }

    // ---- A-inv: inverse levels 8-11 ----
    __syncthreads();
    {
        int e = tid >> 8, i1 = tid & 255;
        int baseA = 4096 * e + (i1 & ~31);
        int mA = (i1 & 31) ^ (i1 >> 5);
#pragma unroll
        for (int j = 0; j < 16; j++) r[j] = S[baseA + 256 * j + (mA ^ (8 * (j & 3)))];
        float2 qA;
        { float sn, cs; __sincosf(C8 * (float)(i1 << 1), &sn, &cs); qA = make_float2(cs, sn); }
        {
            float2 v0 = cmulf2(qA, qA); v0 = cmulf2(v0, v0);   // e^{+i C8*(i1<<3)}
#pragma unroll
            for (int q = 0; q < 4; q++) r4i(r[4 * q], r[4 * q + 1], r[4 * q + 2], r[4 * q + 3], v0);
        }
        {
            float2 v = qA;
#pragma unroll
            for (int jp = 0; jp < 4; jp++) {
                r4i(r[jp], r[jp + 4], r[jp + 8], r[jp + 12], v);
                v = cmulf2(v, RHOc);
            }
        }
#pragma unroll
        for (int j = 0; j < 16; j++) S[baseA + 256 * j + (mA ^ (8 * (j & 3)))] = r[j];
    }

    // ---- Epilogue: inverse level 12 + skip + gelu -> g_T fp16 ----
    __syncthreads();
    float Dh = Dv[h];
    const float inv = 1.0f / (float)MFFT;
    int pA = tid ^ (tid >> 5);
    float2 wb;
    { float sn, cs; __sincosf(C8 * (float)tid, &sn, &cs); wb = make_float2(cs, sn); }
#pragma unroll
    for (int p = 0; p < 8; p++) {
        int addr = (pA ^ ((p & 1) << 4)) + 512 * p;
        float2 a = S[addr], bq = S[addr + 4096];
        float2 t = cmulf2(bq, wb);
        float2 X = caddf2(a, t);
        int g = tid + 512 * p;
        float2 uu = up[g];
        float y0 = X.x * inv + Dh * uu.x;
        float y1 = X.y * inv + Dh * uu.y;
        float q0 = 0.5f * y0 * (1.0f + erff(y0 * 0.70710678118654752440f));
        float q1 = 0.5f * y1 * (1.0f + erff(y1 * 0.70710678118654752440f));
        __half2* gt = (__half2*)g_T + (((size_t)b * 64 + (g >> 6)) * HDIM + h) * 64 + (g & 63);
        *gt = __floats2half2_rn(q0, q1);
        wb = cmulf2(wb, RHOc);
    }
}

// W pack: g_Whl[o][c][0..31] = hi(h=32c+q), [c][32..63] = lo
extern "C" __global__ void __launch_bounds__(256) wpack_kernel(const float* __restrict__ Wm) {
    int i = blockIdx.x * 256 + threadIdx.x;
    int o = i >> 9, h = i & 511;
    float v = Wm[i];
    __half hi = __float2half_rn(v);
    __half lo = __float2half_rn(v - __half2float(hi));
    g_Whl[((size_t)o * 16 + (h >> 5)) * 64 + (h & 31)]      = hi;
    g_Whl[((size_t)o * 16 + (h >> 5)) * 64 + 32 + (h & 31)] = lo;
}

// ---------------- mma.sync GEMM (R13, proven) ----------------
__device__ __forceinline__ uint32_t smem_u32(const void* p) {
    return (uint32_t)__cvta_generic_to_shared(p);
}
__device__ __forceinline__ uint32_t swz(uint32_t off) { return off ^ ((off >> 3) & 0x70); }
__device__ __forceinline__ uint32_t swzB(uint32_t row, uint32_t colb) {
    return row * 256 + (colb ^ ((row & 7) << 4));
}

__device__ __forceinline__ void ldmat4(uint32_t* r, uint32_t addr) {
    asm volatile("ldmatrix.sync.aligned.m8n8.x4.shared.b16 {%0,%1,%2,%3}, [%4];"
                 : "=r"(r[0]), "=r"(r[1]), "=r"(r[2]), "=r"(r[3]) : "r"(addr));
}
__device__ __forceinline__ void ldmat4t(uint32_t* r, uint32_t addr) {
    asm volatile("ldmatrix.sync.aligned.m8n8.x4.trans.shared.b16 {%0,%1,%2,%3}, [%4];"
                 : "=r"(r[0]), "=r"(r[1]), "=r"(r[2]), "=r"(r[3]) : "r"(addr));
}
__device__ __forceinline__ void mma16816(float* d, const uint32_t* a, uint32_t b0, uint32_t b1) {
    asm volatile(
        "mma.sync.aligned.m16n8k16.row.col.f32.f16.f16.f32 "
        "{%0,%1,%2,%3}, {%4,%5,%6,%7}, {%8,%9}, {%0,%1,%2,%3};"
        : "+f"(d[0]), "+f"(d[1]), "+f"(d[2]), "+f"(d[3])
        : "r"(a[0]), "r"(a[1]), "r"(a[2]), "r"(a[3]), "r"(b0), "r"(b1));
}
#define CP16(dst, src) asm volatile("cp.async.cg.shared.global [%0], [%1], 16;" :: "r"(dst), "l"(src) : "memory")
#define CP_COMMIT()    asm volatile("cp.async.commit_group;" ::: "memory")
#define CP_WAIT1()     asm volatile("cp.async.wait_group 1;" ::: "memory")

extern "C" __global__ void __launch_bounds__(256, 2) gemm_mma_kernel(
    const float* __restrict__ bias, float* __restrict__ outp) {
    extern __shared__ char smem[];
    uint32_t sb = smem_u32(smem);
    int t = threadIdx.x;
    int lane = t & 31, wid = t >> 5;
    int warp_m = wid >> 2, warp_n = wid & 3;
    int o0 = blockIdx.x * 128, l0 = blockIdx.y * 128, b = blockIdx.z;

    int a_row = t >> 1, a_half = t & 1;
    const __half* wp = g_Whl + (size_t)(o0 + a_row) * 1024 + a_half * 32;
    int b_row = t >> 3, b_cj = (t & 7) * 2;
    const __half* gpB = g_T + ((size_t)b * 64 + blockIdx.y) * HDIM * 128;

    auto load_chunk = [&](int c) {
        int buf = c % 3;
        uint32_t sA = sb + buf * 24576;
        uint32_t sB = sA + 16384;
        const __half* aw = wp + c * 64;
#pragma unroll
        for (int j = 0; j < 4; j++) {
            uint32_t off = (uint32_t)(a_row * 128 + a_half * 64 + j * 16);
            CP16(sA + swz(off), aw + j * 8);
        }
        const __half* brow = gpB + (size_t)(c * 32 + b_row) * 128 + b_cj * 8;
#pragma unroll
        for (int e2 = 0; e2 < 2; e2++) {
            CP16(sB + swzB((uint32_t)b_row, (uint32_t)((b_cj + e2) * 16)), brow + e2 * 8);
        }
    };

    int a_lrow = (lane & 7) + ((lane >> 3) & 1) * 8;
    int a_lcol = (lane >> 4) * 16;
    uint32_t xorm = (uint32_t)((lane & 7) << 4);
    int bt_row = (lane & 7) + 8 * ((lane >> 3) & 1);
    int bt_colb = 16 * (lane >> 4);

    float acc[4][4][4];
#pragma unroll
    for (int i = 0; i < 4; i++)
#pragma unroll
        for (int j = 0; j < 4; j++)
#pragma unroll
            for (int q = 0; q < 4; q++) acc[i][j][q] = 0.f;

    load_chunk(0);
    CP_COMMIT();
    load_chunk(1);
    CP_COMMIT();

#pragma unroll 1
    for (int c = 0; c < 16; c++) {
        CP_WAIT1();
        __syncthreads();
        if (c + 2 < 16) load_chunk(c + 2);
        CP_COMMIT();
        int buf = c % 3;
        uint32_t sA = sb + buf * 24576;
        uint32_t sB = sA + 16384;
#pragma unroll
        for (int s = 0; s < 2; s++) {
            uint32_t ahi[4][4], alo[4][4];
#pragma unroll
            for (int mt = 0; mt < 4; mt++) {
                uint32_t offh = (uint32_t)((warp_m * 64 + mt * 16 + a_lrow) * 128 + s * 32 + a_lcol);
                uint32_t offl = offh + 64;
                ldmat4(ahi[mt], sA + (offh ^ xorm));
                ldmat4(alo[mt], sA + (offl ^ xorm));
            }
#pragma unroll
            for (int bt = 0; bt < 2; bt++) {
                uint32_t bfr[4];
                uint32_t row = (uint32_t)(16 * s + bt_row);
                uint32_t colb = (uint32_t)(2 * (warp_n * 32 + bt * 16) + bt_colb);
                ldmat4t(bfr, sB + swzB(row, colb));
#pragma unroll
                for (int mt = 0; mt < 4; mt++) {
                    mma16816(acc[mt][bt * 2 + 0], ahi[mt], bfr[0], bfr[1]);
                    mma16816(acc[mt][bt * 2 + 0], alo[mt], bfr[0], bfr[1]);
                    mma16816(acc[mt][bt * 2 + 1], ahi[mt], bfr[2], bfr[3]);
                    mma16816(acc[mt][bt * 2 + 1], alo[mt], bfr[2], bfr[3]);
                }
            }
        }
    }

#pragma unroll
    for (int mt = 0; mt < 4; mt++) {
        int r = o0 + warp_m * 64 + mt * 16 + (lane >> 2);
        float bs0 = bias[r], bs1 = bias[r + 8];
        float* p0 = outp + ((size_t)b * HDIM + r) * LDIM + l0 + warp_n * 32 + (lane & 3) * 2;
        float* p1 = p0 + 8 * LDIM;
#pragma unroll
        for (int nt = 0; nt < 4; nt++) {
            float2 v0 = make_float2(acc[mt][nt][0] + bs0, acc[mt][nt][1] + bs0);
            float2 v1 = make_float2(acc[mt][nt][2] + bs1, acc[mt][nt][3] + bs1);
            *(float2*)(p0 + nt * 8) = v0;
            *(float2*)(p1 + nt * 8) = v1;
        }
    }
}

extern "C" void kernel_launch(void* const* d_in, const int* in_sizes, int n_in,
                              void* d_out, int out_size) {
    const float* u    = (const float*)d_in[0];   // (8,512,8192)
    const float* kin  = (const float*)d_in[1];   // (1,512,8192)
    const float* Dv   = (const float*)d_in[2];   // (1,512)
    const float* Wm   = (const float*)d_in[3];   // (512,512)
    const float* bias = (const float*)d_in[4];   // (512,)
    float* outp = (float*)d_out;                 // (8,512,8192)

    size_t smem = (size_t)MFFT * sizeof(float2);  // 64 KB
    cudaFuncSetAttribute(kf_kernel,   cudaFuncAttributeMaxDynamicSharedMemorySize, (int)smem);
    cudaFuncSetAttribute(conv_kernel, cudaFuncAttributeMaxDynamicSharedMemorySize, (int)smem);
    size_t gsmem = 3 * 24576;                      // 72 KB
    cudaFuncSetAttribute(gemm_mma_kernel, cudaFuncAttributeMaxDynamicSharedMemorySize, (int)gsmem);

    wpack_kernel<<<HDIM * HDIM / 256, 256>>>(Wm);
    kf_kernel<<<HDIM, 512, smem>>>(kin);
    conv_kernel<<<BDIM * HDIM, 512, smem>>>(u, Dv);
    dim3 grid(HDIM / 128, LDIM / 128, BDIM);
    gemm_mma_kernel<<<grid, 256, gsmem>>>(bias, outp);
}

// round 15
// speedup vs baseline: 1.4434x; 1.1203x over previous
#include <cuda_runtime.h>
#include <cuda_fp16.h>
#include <math.h>
#include <stdint.h>

// Problem constants
#define MFFT 8192
#define MH   4096
#define HDIM 512
#define BDIM 8
#define LDIM 8192
#define C8   (6.283185307179586f / 8192.0f)
#define RS2  0.70710678118654752440f
#define RHO_C 0.92387953251128675613f
#define RHO_S 0.38268343236508977173f
#define P16_C 0.98078528040323044913f
#define P16_S 0.19509032201612826785f

// Device scratch
__device__ float2 g_Kf[HDIM * 8193];                       // rfft(k, 16384) per h
__device__ __half g_T[(size_t)BDIM * 64 * HDIM * 128];     // g fp16, [b][l/128][h][l%128]
__device__ __half g_Wh[(size_t)HDIM * HDIM];               // W plain fp16 [o][h]

__device__ __forceinline__ float2 cmulf2(float2 a, float2 b) {
    return make_float2(a.x * b.x - a.y * b.y, a.x * b.y + a.y * b.x);
}
__device__ __forceinline__ float2 caddf2(float2 a, float2 b) { return make_float2(a.x + b.x, a.y + b.y); }
__device__ __forceinline__ float2 csubf2(float2 a, float2 b) { return make_float2(a.x - b.x, a.y - b.y); }
__device__ __forceinline__ float2 conjf2(float2 a) { return make_float2(a.x, -a.y); }
__device__ __forceinline__ int rev13(int k) { return (int)(__brev((unsigned)k) >> 19); }
__device__ __forceinline__ int phys(int i) { return i ^ ((i >> 5) & 31); }

// Proven radix-4 bodies
__device__ __forceinline__ void r4f(float2& A0, float2& A1, float2& A2, float2& A3, float2 w1) {
    float2 w2 = cmulf2(w1, w1);
    float2 s02 = caddf2(A0, A2), d02 = csubf2(A0, A2);
    float2 s13 = caddf2(A1, A3), d13 = csubf2(A1, A3);
    A0 = caddf2(s02, s13);
    A1 = cmulf2(csubf2(s02, s13), w2);
    float2 m  = make_float2(d02.x + d13.y, d02.y - d13.x);
    A2 = cmulf2(m, w1);
    float2 pq = make_float2(d02.x - d13.y, d02.y + d13.x);
    A3 = cmulf2(cmulf2(pq, w1), w2);
}
__device__ __forceinline__ void r4i(float2& A0, float2& A1, float2& A2, float2& A3, float2 v0) {
    float2 w  = cmulf2(v0, v0);
    float2 t1 = cmulf2(A1, w), t3 = cmulf2(A3, w);
    float2 b0 = caddf2(A0, t1), b1 = csubf2(A0, t1);
    float2 b2 = caddf2(A2, t3), b3 = csubf2(A2, t3);
    float2 e = cmulf2(b2, v0), f = cmulf2(b3, v0);
    A0 = caddf2(b0, e);
    A2 = csubf2(b0, e);
    A1 = make_float2(b1.x - f.y, b1.y + f.x);
    A3 = make_float2(b1.x + f.y, b1.y - f.x);
}
__device__ __forceinline__ void spectral_pair(int k, float2 Zk, float2 Zm, const float2* Kf,
                                              float2& outk, float2& outm) {
    float2 cZm = conjf2(Zm);
    float2 E = make_float2(0.5f * (Zk.x + cZm.x), 0.5f * (Zk.y + cZm.y));
    float2 Dd = csubf2(Zk, cZm);
    float2 O = make_float2(0.5f * Dd.y, -0.5f * Dd.x);
    float ang = (-3.14159265358979323846f / 8192.0f) * (float)k;
    float sn, cs; __sincosf(ang, &sn, &cs);
    float2 Wt = make_float2(cs, sn);
    float2 WO = cmulf2(Wt, O);
    float2 Xk = caddf2(E, WO);
    float2 Xm = conjf2(csubf2(E, WO));
    float2 Yk = cmulf2(Xk, Kf[k]);
    float2 Ym = cmulf2(Xm, Kf[MFFT - k]);
    float2 cYm = conjf2(Ym);
    float2 Ep = make_float2(0.5f * (Yk.x + cYm.x), 0.5f * (Yk.y + cYm.y));
    float2 P  = make_float2(0.5f * (Yk.x - cYm.x), 0.5f * (Yk.y - cYm.y));
    float2 Op = cmulf2(conjf2(Wt), P);
    outk = make_float2(Ep.x - Op.y, Ep.y + Op.x);
    outm = make_float2(Ep.x + Op.y, Op.x - Ep.y);
}

// Register radix-16 forward 12 levels (phases A,B,C) — proven in conv since R12/R14.
// Result: 12-level DIF state P in S (bit-reversed at granularity of level-12 pairs).
__device__ void fft12_forward(float2* S, const float2* up, int tid) {
    float2 r[16];
    const float2 RHO = make_float2(RHO_C, -RHO_S);
    // Phase A: levels 0-3
#pragma unroll
    for (int j = 0; j < 8; j++) r[j] = up[tid + 512 * j];
    float2 wA;
    { float sn, cs; __sincosf(-C8 * (float)tid, &sn, &cs); wA = make_float2(cs, sn); }
    {
        float2 w = wA;
#pragma unroll
        for (int jp = 0; jp < 4; jp++) {
            float2 a0 = r[jp], a1 = r[jp + 4];
            float2 w1 = w, w2 = cmulf2(w, w);
            r[jp]      = caddf2(a0, a1);
            r[jp + 4]  = cmulf2(csubf2(a0, a1), w2);
            float2 m   = make_float2(a0.x + a1.y, a0.y - a1.x);
            r[jp + 8]  = cmulf2(m, w1);
            float2 pq  = make_float2(a0.x - a1.y, a0.y + a1.x);
            r[jp + 12] = cmulf2(cmulf2(pq, w1), w2);
            w = cmulf2(w, RHO);
        }
        float2 w4 = cmulf2(wA, wA); w4 = cmulf2(w4, w4);
#pragma unroll
        for (int q = 0; q < 4; q++) r4f(r[4 * q], r[4 * q + 1], r[4 * q + 2], r[4 * q + 3], w4);
    }
    {
        int pA = tid ^ (tid >> 5);
#pragma unroll
        for (int j = 0; j < 16; j++) S[(pA ^ ((j & 1) << 4)) + 512 * j] = r[j];
    }
    // Phase B: levels 4-7
    __syncthreads();
    {
        int bb = tid >> 5, t = tid & 31;
        int baseB = bb * 512;
        int tb = t ^ ((bb & 1) << 4);
#pragma unroll
        for (int j = 0; j < 16; j++) r[j] = S[baseB + 32 * j + (tb ^ j)];
        float2 wB;
        { float sn, cs; __sincosf(-C8 * (float)(t << 4), &sn, &cs); wB = make_float2(cs, sn); }
        {
            float2 w = wB;
#pragma unroll
            for (int jp = 0; jp < 4; jp++) {
                r4f(r[jp], r[jp + 4], r[jp + 8], r[jp + 12], w);
                w = cmulf2(w, RHO);
            }
        }
        float2 w4 = cmulf2(wB, wB); w4 = cmulf2(w4, w4);
#pragma unroll
        for (int q = 0; q < 4; q++) r4f(r[4 * q], r[4 * q + 1], r[4 * q + 2], r[4 * q + 3], w4);
#pragma unroll
        for (int j = 0; j < 16; j++) S[baseB + 32 * j + (tb ^ j)] = r[j];
    }
    // Phase C: levels 8-11
    __syncthreads();
    {
        int b2 = tid >> 1, t2 = tid & 1;
        int baseC = 32 * b2;
        int mC0 = b2 & 31;
#pragma unroll
        for (int j = 0; j < 16; j++) r[j] = S[baseC + ((2 * j + t2) ^ mC0)];
        {
            float2 w = t2 ? make_float2(P16_C, -P16_S) : make_float2(1.f, 0.f);
#pragma unroll
            for (int jp = 0; jp < 4; jp++) {
                r4f(r[jp], r[jp + 4], r[jp + 8], r[jp + 12], w);
                w = cmulf2(w, RHO);
            }
        }
        {
            float2 w1 = t2 ? make_float2(RS2, -RS2) : make_float2(1.f, 0.f);
#pragma unroll
            for (int q = 0; q < 4; q++) r4f(r[4 * q], r[4 * q + 1], r[4 * q + 2], r[4 * q + 3], w1);
        }
#pragma unroll
        for (int j = 0; j < 16; j++) S[baseC + ((2 * j + t2) ^ mC0)] = r[j];
    }
    __syncthreads();
}

// Kernel A: Kf[h] = rfft(k[h], 16384) via register radix-16 + fused level-12 output.
extern "C" __global__ void __launch_bounds__(512, 2) kf_kernel(const float* __restrict__ kin) {
    extern __shared__ float2 sh[];
    float2* S = sh;
    int tid = threadIdx.x;
    int h = blockIdx.x;
    const float2* kp = (const float2*)(kin + (size_t)h * LDIM);
    fft12_forward(S, kp, tid);
    float2* outp = g_Kf + (size_t)h * 8193;
#pragma unroll 1
    for (int p = 0; p < 8; p++) {
        int k = tid + 512 * p;
        if (k == 0) {
            float2 P0 = S[phys(0)], P1 = S[phys(1)];
            float2 Z0 = caddf2(P0, P1);
            float2 Zq = csubf2(P0, P1);          // Z[4096]
            outp[0]    = make_float2(Z0.x + Z0.y, 0.f);
            outp[8192] = make_float2(Z0.x - Z0.y, 0.f);
            outp[4096] = conjf2(Zq);
        } else {
            int rk  = rev13(k);
            int rkt = rev13(MFFT - k);           // odd slot index: rev13(8192-k) = rev13(4096-(k-4096))... use pair form
            // Z[k] = P[rk] + P[rk+1] (rk even); Z[8192-k] = P[rq] - P[rq+1] where rq = rev13(4096-k)
            int rq = rev13(4096 - k);
            (void)rkt;
            float2 Pa = S[phys(rk)], Pb = S[phys(rk + 1)];
            float2 Pc = S[phys(rq)], Pd = S[phys(rq + 1)];
            float2 Zk = caddf2(Pa, Pb);
            float2 Zm = csubf2(Pc, Pd);
            float2 cZm = conjf2(Zm);
            float2 E  = make_float2(0.5f * (Zk.x + cZm.x), 0.5f * (Zk.y + cZm.y));
            float2 Dd = csubf2(Zk, cZm);
            float2 O  = make_float2(0.5f * Dd.y, -0.5f * Dd.x);
            float ang = (-3.14159265358979323846f / 8192.0f) * (float)k;
            float sn, cs; __sincosf(ang, &sn, &cs);
            float2 Wt = make_float2(cs, sn);
            float2 WO = cmulf2(Wt, O);
            outp[k]        = caddf2(E, WO);
            outp[MFFT - k] = conjf2(csubf2(E, WO));
        }
    }
}

// ---------------- Kernel B: register radix-16 conv (R14, proven) ----------------
extern "C" __global__ void __launch_bounds__(512, 2) conv_kernel(
    const float* __restrict__ u, const float* __restrict__ Dv) {
    extern __shared__ float2 sh[];
    float2* S = sh;
    int tid = threadIdx.x;
    int b = blockIdx.x & (BDIM - 1);
    int h = blockIdx.x >> 3;
    const float2* up = (const float2*)(u + ((size_t)b * HDIM + h) * LDIM);
    float2 r[16];
    const float2 RHOc = make_float2(RHO_C, RHO_S);

    fft12_forward(S, up, tid);

    // Spectral stage + fused forward level 12
    const float2* Kf = g_Kf + (size_t)h * 8193;
#pragma unroll 1
    for (int p = 0; p < 4; p++) {
        int k = tid + 512 * p;
        if (k == 0) {
            float2 P0 = S[phys(0)], P1 = S[phys(1)];
            float2 Z0 = caddf2(P0, P1);
            float2 Zq = csubf2(P0, P1);
            float X0 = Z0.x + Z0.y;
            float XM = Z0.x - Z0.y;
            float2 K0 = Kf[0], KM = Kf[8192];
            float2 Y0 = make_float2(X0 * K0.x, X0 * K0.y);
            float2 YM = make_float2(XM * KM.x, XM * KM.y);
            float2 cYM = conjf2(YM);
            float2 Ep = make_float2(0.5f * (Y0.x + cYM.x), 0.5f * (Y0.y + cYM.y));
            float2 Op = make_float2(0.5f * (Y0.x - cYM.x), 0.5f * (Y0.y - cYM.y));
            S[phys(0)] = make_float2(Ep.x - Op.y, Ep.y + Op.x);
            float2 Yq = cmulf2(conjf2(Zq), Kf[4096]);
            S[phys(1)] = conjf2(Yq);
            float2 P2 = S[phys(2)], P3 = S[phys(3)];
            float2 Zk = caddf2(P2, P3);
            float2 Zm = csubf2(P2, P3);
            float2 ok, om;
            spectral_pair(2048, Zk, Zm, Kf, ok, om);
            S[phys(2)] = ok;
            S[phys(3)] = om;
        } else {
            int rk  = rev13(k);
            int rkt = rev13(4096 - k);
            float2 Pa = S[phys(rk)],  Pb = S[phys(rk + 1)];
            float2 Pc = S[phys(rkt)], Pd = S[phys(rkt + 1)];
            float2 Zk   = caddf2(Pa, Pb);
            float2 ZMk  = csubf2(Pc, Pd);
            float2 Zkt  = caddf2(Pc, Pd);
            float2 ZMkt = csubf2(Pa, Pb);
            float2 o1k, o1m, o2k, o2m;
            spectral_pair(k, Zk, ZMk, Kf, o1k, o1m);
            spectral_pair(4096 - k, Zkt, ZMkt, Kf, o2k, o2m);
            S[phys(rk)]      = o1k;
            S[phys(rkt + 1)] = o1m;
            S[phys(rkt)]     = o2k;
            S[phys(rk + 1)]  = o2m;
        }
    }

    // C-inv
    __syncthreads();
    {
        int baseCi = 32 * (tid >> 1);
        int mm = (16 * (tid & 1)) ^ ((tid >> 1) & 31);
#pragma unroll
        for (int j = 0; j < 16; j++) r[j] = S[baseCi + (j ^ mm)];
#pragma unroll
        for (int m2 = 0; m2 < 8; m2++) {
            float2 a = r[2 * m2], bq = r[2 * m2 + 1];
            r[2 * m2]     = caddf2(a, bq);
            r[2 * m2 + 1] = csubf2(a, bq);
        }
#pragma unroll
        for (int q = 0; q < 2; q++)
#pragma unroll
            for (int tq = 0; tq < 2; tq++) {
                float2 v0 = tq ? make_float2(RS2, RS2) : make_float2(1.f, 0.f);
                int o = 8 * q + tq;
                r4i(r[o], r[o + 2], r[o + 4], r[o + 6], v0);
            }
        {
            float2 wb = make_float2(1.f, 0.f);
#pragma unroll
            for (int j = 0; j < 8; j++) {
                float2 t = cmulf2(r[j + 8], wb);
                float2 a = r[j];
                r[j]     = caddf2(a, t);
                r[j + 8] = csubf2(a, t);
                wb = cmulf2(wb, RHOc);
            }
        }
#pragma unroll
        for (int j = 0; j < 16; j++) S[baseCi + (j ^ mm)] = r[j];
    }

    // B-inv
    __syncthreads();
    {
        int c = tid >> 4, i0 = tid & 15;
        int baseBi = 256 * c;
        int mB = i0 ^ (8 * (c & 3));
#pragma unroll
        for (int j = 0; j < 16; j++)
            r[j] = S[baseBi + 32 * (j >> 1) + (mB ^ ((16 * (j & 1)) | (j >> 1)))];
        float2 qB;
        { float sn, cs; __sincosf(C8 * (float)(i0 << 5), &sn, &cs); qB = make_float2(cs, sn); }
        {
            float2 v0 = cmulf2(qB, qB); v0 = cmulf2(v0, v0);
#pragma unroll
            for (int q = 0; q < 4; q++) r4i(r[4 * q], r[4 * q + 1], r[4 * q + 2], r[4 * q + 3], v0);
        }
        {
            float2 v = qB;
#pragma unroll
            for (int jp = 0; jp < 4; jp++) {
                r4i(r[jp], r[jp + 4], r[jp + 8], r[jp + 12], v);
                v = cmulf2(v, RHOc);
            }
        }
#pragma unroll
        for (int j = 0; j < 16; j++)
            S[baseBi + 32 * (j >> 1) + (mB ^ ((16 * (j & 1)) | (j >> 1)))] = r[j];
    }

    // A-inv
    __syncthreads();
    {
        int e = tid >> 8, i1 = tid & 255;
        int baseA = 4096 * e + (i1 & ~31);
        int mA = (i1 & 31) ^ (i1 >> 5);
#pragma unroll
        for (int j = 0; j < 16; j++) r[j] = S[baseA + 256 * j + (mA ^ (8 * (j & 3)))];
        float2 qA;
        { float sn, cs; __sincosf(C8 * (float)(i1 << 1), &sn, &cs); qA = make_float2(cs, sn); }
        {
            float2 v0 = cmulf2(qA, qA); v0 = cmulf2(v0, v0);
#pragma unroll
            for (int q = 0; q < 4; q++) r4i(r[4 * q], r[4 * q + 1], r[4 * q + 2], r[4 * q + 3], v0);
        }
        {
            float2 v = qA;
#pragma unroll
            for (int jp = 0; jp < 4; jp++) {
                r4i(r[jp], r[jp + 4], r[jp + 8], r[jp + 12], v);
                v = cmulf2(v, RHOc);
            }
        }
#pragma unroll
        for (int j = 0; j < 16; j++) S[baseA + 256 * j + (mA ^ (8 * (j & 3)))] = r[j];
    }

    // Epilogue
    __syncthreads();
    float Dh = Dv[h];
    const float inv = 1.0f / (float)MFFT;
    int pA = tid ^ (tid >> 5);
    float2 wb;
    { float sn, cs; __sincosf(C8 * (float)tid, &sn, &cs); wb = make_float2(cs, sn); }
#pragma unroll
    for (int p = 0; p < 8; p++) {
        int addr = (pA ^ ((p & 1) << 4)) + 512 * p;
        float2 a = S[addr], bq = S[addr + 4096];
        float2 t = cmulf2(bq, wb);
        float2 X = caddf2(a, t);
        int g = tid + 512 * p;
        float2 uu = up[g];
        float y0 = X.x * inv + Dh * uu.x;
        float y1 = X.y * inv + Dh * uu.y;
        float q0 = 0.5f * y0 * (1.0f + erff(y0 * 0.70710678118654752440f));
        float q1 = 0.5f * y1 * (1.0f + erff(y1 * 0.70710678118654752440f));
        __half2* gt = (__half2*)g_T + (((size_t)b * 64 + (g >> 6)) * HDIM + h) * 64 + (g & 63);
        *gt = __floats2half2_rn(q0, q1);
        wb = cmulf2(wb, RHOc);
    }
}

// W pack: plain fp16
extern "C" __global__ void __launch_bounds__(256) wpack_kernel(const float* __restrict__ Wm) {
    int i = blockIdx.x * 256 + threadIdx.x;
    g_Wh[i] = __float2half_rn(Wm[i]);
}

// ---------------- mma.sync GEMM: plain fp16, 64-h double-chunk stages ----------------
__device__ __forceinline__ uint32_t smem_u32(const void* p) {
    return (uint32_t)__cvta_generic_to_shared(p);
}
__device__ __forceinline__ uint32_t swz(uint32_t off) { return off ^ ((off >> 3) & 0x70); }
__device__ __forceinline__ uint32_t swzB(uint32_t row, uint32_t colb) {
    return row * 256 + (colb ^ ((row & 7) << 4));
}

__device__ __forceinline__ void ldmat4(uint32_t* r, uint32_t addr) {
    asm volatile("ldmatrix.sync.aligned.m8n8.x4.shared.b16 {%0,%1,%2,%3}, [%4];"
                 : "=r"(r[0]), "=r"(r[1]), "=r"(r[2]), "=r"(r[3]) : "r"(addr));
}
__device__ __forceinline__ void ldmat4t(uint32_t* r, uint32_t addr) {
    asm volatile("ldmatrix.sync.aligned.m8n8.x4.trans.shared.b16 {%0,%1,%2,%3}, [%4];"
                 : "=r"(r[0]), "=r"(r[1]), "=r"(r[2]), "=r"(r[3]) : "r"(addr));
}
__device__ __forceinline__ void mma16816(float* d, const uint32_t* a, uint32_t b0, uint32_t b1) {
    asm volatile(
        "mma.sync.aligned.m16n8k16.row.col.f32.f16.f16.f32 "
        "{%0,%1,%2,%3}, {%4,%5,%6,%7}, {%8,%9}, {%0,%1,%2,%3};"
        : "+f"(d[0]), "+f"(d[1]), "+f"(d[2]), "+f"(d[3])
        : "r"(a[0]), "r"(a[1]), "r"(a[2]), "r"(a[3]), "r"(b0), "r"(b1));
}
#define CP16(dst, src) asm volatile("cp.async.cg.shared.global [%0], [%1], 16;" :: "r"(dst), "l"(src) : "memory")
#define CP_COMMIT()    asm volatile("cp.async.commit_group;" ::: "memory")
#define CP_WAIT1()     asm volatile("cp.async.wait_group 1;" ::: "memory")

// Stage dc covers h in [dc*64, dc*64+64). A tile: 128 rows(o) x 128B (64 fp16), swz.
// B tile: 64 rows(kh) x 256B (128 fp16 l), swzB. 3 stages x 32KB = 96KB.
extern "C" __global__ void __launch_bounds__(256, 2) gemm_mma_kernel(
    const float* __restrict__ bias, float* __restrict__ outp) {
    extern __shared__ char smem[];
    uint32_t sb = smem_u32(smem);
    int t = threadIdx.x;
    int lane = t & 31, wid = t >> 5;
    int warp_m = wid >> 2, warp_n = wid & 3;   // 2 x 4 warp grid; warp tile 64x32
    int o0 = blockIdx.x * 128, l0 = blockIdx.y * 128, b = blockIdx.z;

    int a_row = t >> 1, a_half = t & 1;
    const __half* wp = g_Wh + (size_t)(o0 + a_row) * HDIM + a_half * 32;
    int b_row = t >> 2, b_c4 = t & 3;          // 64 rows, 4 threads/row, 64B each
    const __half* gpB = g_T + ((size_t)b * 64 + blockIdx.y) * HDIM * 128;

    auto load_chunk = [&](int dc) {
        int buf = dc % 3;
        uint32_t sA = sb + buf * 32768;
        uint32_t sB = sA + 16384;
        const __half* aw = wp + dc * 64;
#pragma unroll
        for (int j = 0; j < 4; j++) {
            uint32_t off = (uint32_t)(a_row * 128 + a_half * 64 + j * 16);
            CP16(sA + swz(off), aw + j * 8);
        }
        const __half* brow = gpB + (size_t)(dc * 64 + b_row) * 128 + b_c4 * 32;
#pragma unroll
        for (int e2 = 0; e2 < 4; e2++) {
            uint32_t colb = (uint32_t)(b_c4 * 64 + e2 * 16);
            CP16(sB + swzB((uint32_t)b_row, colb), brow + e2 * 8);
        }
    };

    int a_lrow = (lane & 7) + ((lane >> 3) & 1) * 8;
    int a_lcol = (lane >> 4) * 16;
    uint32_t xorm = (uint32_t)((lane & 7) << 4);
    int bt_row = (lane & 7) + 8 * ((lane >> 3) & 1);
    int bt_colb = 16 * (lane >> 4);

    float acc[4][4][4];
#pragma unroll
    for (int i = 0; i < 4; i++)
#pragma unroll
        for (int j = 0; j < 4; j++)
#pragma unroll
            for (int q = 0; q < 4; q++) acc[i][j][q] = 0.f;

    load_chunk(0);
    CP_COMMIT();
    load_chunk(1);
    CP_COMMIT();

#pragma unroll 1
    for (int dc = 0; dc < 8; dc++) {
        CP_WAIT1();
        __syncthreads();
        if (dc + 2 < 8) load_chunk(dc + 2);
        CP_COMMIT();
        int buf = dc % 3;
        uint32_t sA = sb + buf * 32768;
        uint32_t sB = sA + 16384;
#pragma unroll
        for (int st = 0; st < 4; st++) {     // k16 steps: kh = dc*64 + st*16
            int cc = st >> 1, sub = st & 1;
            uint32_t afr[4][4];
#pragma unroll
            for (int mt = 0; mt < 4; mt++) {
                uint32_t off = (uint32_t)((warp_m * 64 + mt * 16 + a_lrow) * 128
                                          + cc * 64 + sub * 32 + a_lcol);
                ldmat4(afr[mt], sA + (off ^ xorm));
            }
#pragma unroll
            for (int bt = 0; bt < 2; bt++) {
                uint32_t bfr[4];
                uint32_t row = (uint32_t)(st * 16 + bt_row);
                uint32_t colb = (uint32_t)(2 * (warp_n * 32 + bt * 16) + bt_colb);
                ldmat4t(bfr, sB + swzB(row, colb));
#pragma unroll
                for (int mt = 0; mt < 4; mt++) {
                    mma16816(acc[mt][bt * 2 + 0], afr[mt], bfr[0], bfr[1]);
                    mma16816(acc[mt][bt * 2 + 1], afr[mt], bfr[2], bfr[3]);
                }
            }
        }
    }

    // Epilogue
#pragma unroll
    for (int mt = 0; mt < 4; mt++) {
        int r = o0 + warp_m * 64 + mt * 16 + (lane >> 2);
        float bs0 = bias[r], bs1 = bias[r + 8];
        float* p0 = outp + ((size_t)b * HDIM + r) * LDIM + l0 + warp_n * 32 + (lane & 3) * 2;
        float* p1 = p0 + 8 * LDIM;
#pragma unroll
        for (int nt = 0; nt < 4; nt++) {
            float2 v0 = make_float2(acc[mt][nt][0] + bs0, acc[mt][nt][1] + bs0);
            float2 v1 = make_float2(acc[mt][nt][2] + bs1, acc[mt][nt][3] + bs1);
            *(float2*)(p0 + nt * 8) = v0;
            *(float2*)(p1 + nt * 8) = v1;
        }
    }
}

extern "C" void kernel_launch(void* const* d_in, const int* in_sizes, int n_in,
                              void* d_out, int out_size) {
    const float* u    = (const float*)d_in[0];   // (8,512,8192)
    const float* kin  = (const float*)d_in[1];   // (1,512,8192)
    const float* Dv   = (const float*)d_in[2];   // (1,512)
    const float* Wm   = (const float*)d_in[3];   // (512,512)
    const float* bias = (const float*)d_in[4];   // (512,)
    float* outp = (float*)d_out;                 // (8,512,8192)

    size_t smem = (size_t)MFFT * sizeof(float2);  // 64 KB
    cudaFuncSetAttribute(kf_kernel,   cudaFuncAttributeMaxDynamicSharedMemorySize, (int)smem);
    cudaFuncSetAttribute(conv_kernel, cudaFuncAttributeMaxDynamicSharedMemorySize, (int)smem);
    size_t gsmem = 3 * 32768;                      // 96 KB
    cudaFuncSetAttribute(gemm_mma_kernel, cudaFuncAttributeMaxDynamicSharedMemorySize, (int)gsmem);

    wpack_kernel<<<HDIM * HDIM / 256, 256>>>(Wm);
    kf_kernel<<<HDIM, 512, smem>>>(kin);
    conv_kernel<<<BDIM * HDIM, 512, smem>>>(u, Dv);
    dim3 grid(HDIM / 128, LDIM / 128, BDIM);
    gemm_mma_kernel<<<grid, 256, gsmem>>>(bias, outp);
}